// round 12
// baseline (speedup 1.0000x reference)
#include <cuda_runtime.h>
#include <cuda_fp16.h>
#include <cstdint>

// ---------------------------------------------------------------------------
// PerceiverAttention, sm_103 — Round 11:
//   * KV GEMM reverted to R9 config (128x128, (256,2), 3-stage) — R10 regressed
//   * multi-stream fork/join inside graph capture: weight transposes + Q GEMM
//     overlap with LN / KV GEMM
// ---------------------------------------------------------------------------

#define BATCH 8
#define N1 4096
#define N2 64
#define NKEYS 4160
#define DIM 1024
#define HEADS 16
#define DH 64
#define MROWS (BATCH * NKEYS)   // 33280
#define NSPLIT 5
#define CH_PER_SPLIT 13

__device__ __half g_kvin[(size_t)MROWS * DIM];
__device__ __half g_lnh [(size_t)BATCH * N2 * DIM];
__device__ __half g_qh  [(size_t)BATCH * N2 * DIM];
__device__ __half g_kvh [(size_t)MROWS * 2 * DIM];
__device__ __half g_attnh[(size_t)BATCH * N2 * DIM];
__device__ __half g_wkvT[(size_t)2 * DIM * DIM];
__device__ __half g_wqT [(size_t)DIM * DIM];
__device__ __half g_woT [(size_t)DIM * DIM];
__device__ float  g_pO  [(size_t)BATCH * HEADS * NSPLIT * N2 * DH];
__device__ float  g_pml [(size_t)BATCH * HEADS * NSPLIT * 2 * N2];

// ---------------------------------------------------------------------------
// Helpers
// ---------------------------------------------------------------------------
__device__ __forceinline__ uint32_t smem_u32(const void* p) {
    uint32_t a;
    asm("{ .reg .u64 t; cvta.to.shared.u64 t, %1; cvt.u32.u64 %0, t; }" : "=r"(a) : "l"(p));
    return a;
}
__device__ __forceinline__ void cp_async16(uint32_t dst, const void* src) {
    asm volatile("cp.async.cg.shared.global [%0], [%1], 16;" :: "r"(dst), "l"(src));
}
__device__ __forceinline__ void cp_commit() {
    asm volatile("cp.async.commit_group;" ::: "memory");
}
template <int N>
__device__ __forceinline__ void cp_wait() {
    asm volatile("cp.async.wait_group %0;" :: "n"(N) : "memory");
}
__device__ __forceinline__ void mma_f16(float* d, const uint32_t* a, const uint32_t* b) {
    asm volatile(
        "mma.sync.aligned.m16n8k16.row.col.f32.f16.f16.f32 "
        "{%0,%1,%2,%3}, {%4,%5,%6,%7}, {%8,%9}, {%0,%1,%2,%3};"
        : "+f"(d[0]), "+f"(d[1]), "+f"(d[2]), "+f"(d[3])
        : "r"(a[0]), "r"(a[1]), "r"(a[2]), "r"(a[3]), "r"(b[0]), "r"(b[1]));
}
__device__ __forceinline__ void ldm_x4(uint32_t* r, uint32_t addr) {
    asm volatile("ldmatrix.sync.aligned.m8n8.x4.shared.b16 {%0,%1,%2,%3}, [%4];"
        : "=r"(r[0]), "=r"(r[1]), "=r"(r[2]), "=r"(r[3]) : "r"(addr));
}
__device__ __forceinline__ void ldm_x4_t(uint32_t* r, uint32_t addr) {
    asm volatile("ldmatrix.sync.aligned.m8n8.x4.trans.shared.b16 {%0,%1,%2,%3}, [%4];"
        : "=r"(r[0]), "=r"(r[1]), "=r"(r[2]), "=r"(r[3]) : "r"(addr));
}
__device__ __forceinline__ uint32_t pack_h2(float a, float b) {
    __half2 h = __floats2half2_rn(a, b);
    return *reinterpret_cast<uint32_t*>(&h);
}
__device__ __forceinline__ void store_pair(float* p, float a, float b) {
    *reinterpret_cast<float2*>(p) = make_float2(a, b);
}
__device__ __forceinline__ void store_pair(__half* p, float a, float b) {
    *reinterpret_cast<__half2*>(p) = make_half2(__float2half_rn(a), __float2half_rn(b));
}

// ---------------------------------------------------------------------------
// Weight transpose + fp16 round
// ---------------------------------------------------------------------------
__global__ __launch_bounds__(256) void transpose_kernel(
    const float* __restrict__ in, __half* __restrict__ out, int ncols)
{
    __shared__ float t[32][33];
    const int bx = blockIdx.x * 32;
    const int by = blockIdx.y * 32;
    const int x = threadIdx.x;
    const int y = threadIdx.y;
    #pragma unroll
    for (int i = 0; i < 32; i += 8)
        t[y + i][x] = in[(size_t)(by + y + i) * ncols + bx + x];
    __syncthreads();
    #pragma unroll
    for (int i = 0; i < 32; i += 8)
        out[(size_t)(bx + y + i) * DIM + by + x] = __float2half_rn(t[x][y + i]);
}

// ---------------------------------------------------------------------------
// LayerNorm -> half outputs. 2 rows per block; 128 threads/row.
// ---------------------------------------------------------------------------
__global__ __launch_bounds__(256) void ln_kernel(
    const float* __restrict__ x, const float* __restrict__ lat,
    const float* __restrict__ g1, const float* __restrict__ b1,
    const float* __restrict__ g2, const float* __restrict__ b2)
{
    __shared__ float red[16];
    const int half = threadIdx.x >> 7;
    const int tl   = threadIdx.x & 127;
    const int wid  = threadIdx.x >> 5;
    const int lane = threadIdx.x & 31;

    const int r  = blockIdx.x * 2 + half;
    const int bb = r / NKEYS;
    const int i  = r - bb * NKEYS;

    const float* src;
    const float* g;
    const float* be;
    __half* dst2 = nullptr;
    if (i < N1) {
        src = x + ((size_t)bb * N1 + i) * DIM;
        g = g1; be = b1;
    } else {
        const int j = i - N1;
        src = lat + ((size_t)bb * N2 + j) * DIM;
        g = g2; be = b2;
        dst2 = g_lnh + ((size_t)bb * N2 + j) * DIM;
    }
    __half* dst = g_kvin + (size_t)r * DIM;

    const float4* s4 = reinterpret_cast<const float4*>(src);
    float4 v0 = s4[tl * 2];
    float4 v1 = s4[tl * 2 + 1];
    float s  = v0.x + v0.y + v0.z + v0.w + v1.x + v1.y + v1.z + v1.w;
    float sq = v0.x*v0.x + v0.y*v0.y + v0.z*v0.z + v0.w*v0.w
             + v1.x*v1.x + v1.y*v1.y + v1.z*v1.z + v1.w*v1.w;
    #pragma unroll
    for (int o = 16; o > 0; o >>= 1) {
        s  += __shfl_xor_sync(0xffffffffu, s, o);
        sq += __shfl_xor_sync(0xffffffffu, sq, o);
    }
    if (lane == 0) { red[wid * 2] = s; red[wid * 2 + 1] = sq; }
    __syncthreads();
    const int wb = half * 4;
    float S  = red[(wb+0)*2] + red[(wb+1)*2] + red[(wb+2)*2] + red[(wb+3)*2];
    float SQ = red[(wb+0)*2+1] + red[(wb+1)*2+1] + red[(wb+2)*2+1] + red[(wb+3)*2+1];

    const float mu   = S * (1.0f / DIM);
    const float var  = SQ * (1.0f / DIM) - mu * mu;
    const float rstd = rsqrtf(var + 1e-5f);

    const float4* g4 = reinterpret_cast<const float4*>(g);
    const float4* b4 = reinterpret_cast<const float4*>(be);
    float4 gv0 = g4[tl * 2], gv1 = g4[tl * 2 + 1];
    float4 bv0 = b4[tl * 2], bv1 = b4[tl * 2 + 1];

    uint4 u;
    __half2* hp = reinterpret_cast<__half2*>(&u);
    hp[0] = make_half2(__float2half_rn((v0.x - mu) * rstd * gv0.x + bv0.x),
                       __float2half_rn((v0.y - mu) * rstd * gv0.y + bv0.y));
    hp[1] = make_half2(__float2half_rn((v0.z - mu) * rstd * gv0.z + bv0.z),
                       __float2half_rn((v0.w - mu) * rstd * gv0.w + bv0.w));
    hp[2] = make_half2(__float2half_rn((v1.x - mu) * rstd * gv1.x + bv1.x),
                       __float2half_rn((v1.y - mu) * rstd * gv1.y + bv1.y));
    hp[3] = make_half2(__float2half_rn((v1.z - mu) * rstd * gv1.z + bv1.z),
                       __float2half_rn((v1.w - mu) * rstd * gv1.w + bv1.w));
    reinterpret_cast<uint4*>(dst)[tl] = u;
    if (dst2) reinterpret_cast<uint4*>(dst2)[tl] = u;
}

// ---------------------------------------------------------------------------
// fp16 mma.sync GEMM (128x128 tile) — R9 config
// ---------------------------------------------------------------------------
#define PADH 72
#define TILE_H (128 * PADH)
#define NSTAGE 3
#define GEMM_SMEM_BYTES (NSTAGE * 2 * TILE_H * 2)   // 110592

template <typename OutT>
__global__ __launch_bounds__(256, 2) void gemm_tc(
    const __half* __restrict__ A, const __half* __restrict__ Bt,
    OutT* __restrict__ C, int ldc)
{
    extern __shared__ __half smh[];
    const uint32_t sb = smem_u32(smh);

    const int tid  = threadIdx.x;
    const int wid  = tid >> 5;
    const int lane = tid & 31;
    const int wm = wid & 3;
    const int wn = wid >> 2;
    const int m0 = blockIdx.y * 128;
    const int n0 = blockIdx.x * 128;

    const __half* ga = A  + (size_t)m0 * DIM;
    const __half* gb = Bt + (size_t)n0 * DIM;

    const int lr = tid >> 3;
    const int lc = tid & 7;

    float acc[2][8][4];
    #pragma unroll
    for (int i = 0; i < 2; i++)
        #pragma unroll
        for (int j = 0; j < 8; j++)
            #pragma unroll
            for (int q = 0; q < 4; q++) acc[i][j][q] = 0.f;

    const uint32_t a_off = (uint32_t)(wm * 32 + (lane & 15)) * PADH + (lane >> 4) * 8;
    const uint32_t b_off = (uint32_t)(wn * 64 + ((lane >> 4) << 3) + (lane & 7)) * PADH
                         + ((lane >> 3) & 1) * 8;

    auto load_tile = [&](int chunk, int stage) {
        const uint32_t abase = sb + (uint32_t)stage * 2 * TILE_H * 2;
        const uint32_t bbase = abase + TILE_H * 2;
        const int k0 = chunk * 64;
        #pragma unroll
        for (int i = 0; i < 4; i++) {
            const int r = lr + i * 32;
            cp_async16(abase + (r * PADH + lc * 8) * 2, ga + (size_t)r * DIM + k0 + lc * 8);
        }
        #pragma unroll
        for (int i = 0; i < 4; i++) {
            const int r = lr + i * 32;
            cp_async16(bbase + (r * PADH + lc * 8) * 2, gb + (size_t)r * DIM + k0 + lc * 8);
        }
        cp_commit();
    };

    const int NCHUNK = DIM / 64;   // 16
    load_tile(0, 0);
    load_tile(1, 1);

    for (int c = 0; c < NCHUNK; c++) {
        const int stage = c % NSTAGE;
        if (c + 2 < NCHUNK) { load_tile(c + 2, (c + 2) % NSTAGE); cp_wait<1>(); }
        else                { cp_wait<0>(); }
        __syncthreads();

        const uint32_t sA = sb + (uint32_t)stage * 2 * TILE_H * 2;
        const uint32_t sB = sA + TILE_H * 2;

        #pragma unroll
        for (int kk = 0; kk < 4; kk++) {
            uint32_t af[2][4], bf[8][2];
            #pragma unroll
            for (int mt = 0; mt < 2; mt++)
                ldm_x4(af[mt], sA + (a_off + (uint32_t)(mt * 16) * PADH + kk * 16) * 2);
            #pragma unroll
            for (int p = 0; p < 4; p++) {
                uint32_t r4[4];
                ldm_x4(r4, sB + (b_off + (uint32_t)(p * 16) * PADH + kk * 16) * 2);
                bf[2 * p][0]     = r4[0];
                bf[2 * p][1]     = r4[1];
                bf[2 * p + 1][0] = r4[2];
                bf[2 * p + 1][1] = r4[3];
            }
            #pragma unroll
            for (int mt = 0; mt < 2; mt++)
                #pragma unroll
                for (int nt = 0; nt < 8; nt++)
                    mma_f16(acc[mt][nt], af[mt], bf[nt]);
        }
        __syncthreads();
    }

    #pragma unroll
    for (int mt = 0; mt < 2; mt++) {
        const int row = m0 + wm * 32 + mt * 16 + (lane >> 2);
        #pragma unroll
        for (int nt = 0; nt < 8; nt++) {
            const int col = n0 + wn * 64 + nt * 8 + (lane & 3) * 2;
            store_pair(C + (size_t)row * ldc + col, acc[mt][nt][0], acc[mt][nt][1]);
            store_pair(C + (size_t)(row + 8) * ldc + col, acc[mt][nt][2], acc[mt][nt][3]);
        }
    }
}

// ---------------------------------------------------------------------------
// Small-tile fp16 GEMM (64x64 CTA tile) for 512-row GEMMs
// ---------------------------------------------------------------------------
#define TILE_HS (64 * PADH)
#define GEMM_S_SMEM_BYTES (NSTAGE * 2 * TILE_HS * 2)   // 55296

template <typename OutT>
__global__ __launch_bounds__(256, 2) void gemm_tc_s(
    const __half* __restrict__ A, const __half* __restrict__ Bt,
    OutT* __restrict__ C, int ldc)
{
    extern __shared__ __half smh[];
    const uint32_t sb = smem_u32(smh);

    const int tid  = threadIdx.x;
    const int wid  = tid >> 5;
    const int lane = tid & 31;
    const int wm = wid & 3;
    const int wn = wid >> 2;
    const int m0 = blockIdx.y * 64;
    const int n0 = blockIdx.x * 64;

    const __half* ga = A  + (size_t)m0 * DIM;
    const __half* gb = Bt + (size_t)n0 * DIM;

    const int lr = tid >> 3;
    const int lc = tid & 7;

    float acc[4][4];
    #pragma unroll
    for (int j = 0; j < 4; j++)
        #pragma unroll
        for (int q = 0; q < 4; q++) acc[j][q] = 0.f;

    const uint32_t a_off = (uint32_t)(wm * 16 + (lane & 15)) * PADH + (lane >> 4) * 8;
    const uint32_t b_off = (uint32_t)(wn * 32 + ((lane >> 4) << 3) + (lane & 7)) * PADH
                         + ((lane >> 3) & 1) * 8;

    auto load_tile = [&](int chunk, int stage) {
        const uint32_t abase = sb + (uint32_t)stage * 2 * TILE_HS * 2;
        const uint32_t bbase = abase + TILE_HS * 2;
        const int k0 = chunk * 64;
        #pragma unroll
        for (int i = 0; i < 2; i++) {
            const int r = lr + i * 32;
            cp_async16(abase + (r * PADH + lc * 8) * 2, ga + (size_t)r * DIM + k0 + lc * 8);
        }
        #pragma unroll
        for (int i = 0; i < 2; i++) {
            const int r = lr + i * 32;
            cp_async16(bbase + (r * PADH + lc * 8) * 2, gb + (size_t)r * DIM + k0 + lc * 8);
        }
        cp_commit();
    };

    const int NCHUNK = DIM / 64;
    load_tile(0, 0);
    load_tile(1, 1);

    for (int c = 0; c < NCHUNK; c++) {
        const int stage = c % NSTAGE;
        if (c + 2 < NCHUNK) { load_tile(c + 2, (c + 2) % NSTAGE); cp_wait<1>(); }
        else                { cp_wait<0>(); }
        __syncthreads();

        const uint32_t sA = sb + (uint32_t)stage * 2 * TILE_HS * 2;
        const uint32_t sB = sA + TILE_HS * 2;

        #pragma unroll
        for (int kk = 0; kk < 4; kk++) {
            uint32_t af[4], bf[4][2];
            ldm_x4(af, sA + (a_off + kk * 16) * 2);
            #pragma unroll
            for (int p = 0; p < 2; p++) {
                uint32_t r4[4];
                ldm_x4(r4, sB + (b_off + (uint32_t)(p * 16) * PADH + kk * 16) * 2);
                bf[2 * p][0]     = r4[0];
                bf[2 * p][1]     = r4[1];
                bf[2 * p + 1][0] = r4[2];
                bf[2 * p + 1][1] = r4[3];
            }
            #pragma unroll
            for (int nt = 0; nt < 4; nt++)
                mma_f16(acc[nt], af, bf[nt]);
        }
        __syncthreads();
    }

    const int row = m0 + wm * 16 + (lane >> 2);
    #pragma unroll
    for (int nt = 0; nt < 4; nt++) {
        const int col = n0 + wn * 32 + nt * 8 + (lane & 3) * 2;
        store_pair(C + (size_t)row * ldc + col, acc[nt][0], acc[nt][1]);
        store_pair(C + (size_t)(row + 8) * ldc + col, acc[nt][2], acc[nt][3]);
    }
}

// ---------------------------------------------------------------------------
// Split-K flash attention on fp16 mma.sync (unchanged)
// ---------------------------------------------------------------------------
#define APAD 72

__global__ __launch_bounds__(128) void attn_partial(const float* __restrict__ mask)
{
    __shared__ __half qs [64 * APAD];
    __shared__ __half ks [64 * APAD];
    __shared__ __half vsk[64 * APAD];
    __shared__ float bias[64];

    const int h = blockIdx.x;
    const int b = blockIdx.y;
    const int sp = blockIdx.z;
    const int bh = b * HEADS + h;
    const int tid = threadIdx.x;
    const int wid = tid >> 5;
    const int lane = tid & 31;
    const uint32_t sq = smem_u32(qs);
    const uint32_t sk = smem_u32(ks);
    const uint32_t sv = smem_u32(vsk);

    {
        const int q = tid >> 1;
        const int d0 = (tid & 1) * 32;
        const uint4* src = reinterpret_cast<const uint4*>(
            g_qh + (size_t)(b * N2 + q) * DIM + h * DH + d0);
        const __half2 s2 = __half2half2(__float2half(0.125f));
        #pragma unroll
        for (int i = 0; i < 4; i++) {
            uint4 u = src[i];
            __half2* hp = reinterpret_cast<__half2*>(&u);
            #pragma unroll
            for (int j = 0; j < 4; j++) hp[j] = __hmul2(hp[j], s2);
            *reinterpret_cast<uint4*>(qs + q * APAD + d0 + i * 8) = u;
        }
    }

    float o[8][4];
    #pragma unroll
    for (int j = 0; j < 8; j++)
        #pragma unroll
        for (int q = 0; q < 4; q++) o[j][q] = 0.f;
    float m0r = -1e30f, m1r = -1e30f, l0r = 0.f, l1r = 0.f;

    const uint32_t a_off = (uint32_t)(wid * 16 + (lane & 15)) * APAD + (lane >> 4) * 8;
    const uint32_t b_off = (uint32_t)(((lane >> 4) << 3) + (lane & 7)) * APAD
                         + ((lane >> 3) & 1) * 8;
    const uint32_t t_off = (uint32_t)(((lane >> 3) & 1) * 8 + (lane & 7)) * APAD
                         + (lane >> 4) * 8;
    const int tg = lane & 3;

    for (int cc = 0; cc < CH_PER_SPLIT; cc++) {
        const int key0 = (sp * CH_PER_SPLIT + cc) * 64;
        __syncthreads();

        {
            const int row = tid >> 1;
            const int cb = (tid & 1) * 4;
            const __half* ksrc = g_kvh + ((size_t)(b * NKEYS) + key0 + row) * (2 * DIM) + h * DH;
            const __half* vsrc = ksrc + DIM;
            #pragma unroll
            for (int i = 0; i < 4; i++)
                cp_async16(sk + (row * APAD + (cb + i) * 8) * 2, ksrc + (cb + i) * 8);
            #pragma unroll
            for (int i = 0; i < 4; i++)
                cp_async16(sv + (row * APAD + (cb + i) * 8) * 2, vsrc + (cb + i) * 8);
            cp_commit();
        }
        if (tid < 64) {
            const int kg = key0 + tid;
            bias[tid] = (kg < N1) ? (mask[(size_t)b * N1 + kg] - 1.0f) * 100.0f : 0.f;
        }
        cp_wait<0>();
        __syncthreads();

        float s[8][4];
        #pragma unroll
        for (int j = 0; j < 8; j++)
            #pragma unroll
            for (int q = 0; q < 4; q++) s[j][q] = 0.f;
        #pragma unroll
        for (int kk = 0; kk < 4; kk++) {
            uint32_t af[4], bf[8][2];
            ldm_x4(af, sq + (a_off + kk * 16) * 2);
            #pragma unroll
            for (int p = 0; p < 4; p++) {
                uint32_t r4[4];
                ldm_x4(r4, sk + (b_off + (uint32_t)(p * 16) * APAD + kk * 16) * 2);
                bf[2 * p][0]     = r4[0];
                bf[2 * p][1]     = r4[1];
                bf[2 * p + 1][0] = r4[2];
                bf[2 * p + 1][1] = r4[3];
            }
            #pragma unroll
            for (int nt = 0; nt < 8; nt++)
                mma_f16(s[nt], af, bf[nt]);
        }

        float c0 = -1e30f, c1 = -1e30f;
        #pragma unroll
        for (int nt = 0; nt < 8; nt++) {
            const float b0 = bias[nt * 8 + 2 * tg];
            const float b1 = bias[nt * 8 + 2 * tg + 1];
            s[nt][0] += b0; s[nt][1] += b1; s[nt][2] += b0; s[nt][3] += b1;
            c0 = fmaxf(c0, fmaxf(s[nt][0], s[nt][1]));
            c1 = fmaxf(c1, fmaxf(s[nt][2], s[nt][3]));
        }
        c0 = fmaxf(c0, __shfl_xor_sync(0xffffffffu, c0, 1));
        c0 = fmaxf(c0, __shfl_xor_sync(0xffffffffu, c0, 2));
        c1 = fmaxf(c1, __shfl_xor_sync(0xffffffffu, c1, 1));
        c1 = fmaxf(c1, __shfl_xor_sync(0xffffffffu, c1, 2));

        const float mn0 = fmaxf(m0r, c0);
        const float mn1 = fmaxf(m1r, c1);
        const float al0 = __expf(m0r - mn0);
        const float al1 = __expf(m1r - mn1);
        float cs0 = 0.f, cs1 = 0.f;
        #pragma unroll
        for (int nt = 0; nt < 8; nt++) {
            s[nt][0] = __expf(s[nt][0] - mn0); cs0 += s[nt][0];
            s[nt][1] = __expf(s[nt][1] - mn0); cs0 += s[nt][1];
            s[nt][2] = __expf(s[nt][2] - mn1); cs1 += s[nt][2];
            s[nt][3] = __expf(s[nt][3] - mn1); cs1 += s[nt][3];
        }
        cs0 += __shfl_xor_sync(0xffffffffu, cs0, 1);
        cs0 += __shfl_xor_sync(0xffffffffu, cs0, 2);
        cs1 += __shfl_xor_sync(0xffffffffu, cs1, 1);
        cs1 += __shfl_xor_sync(0xffffffffu, cs1, 2);
        l0r = l0r * al0 + cs0; m0r = mn0;
        l1r = l1r * al1 + cs1; m1r = mn1;
        #pragma unroll
        for (int nt = 0; nt < 8; nt++) {
            o[nt][0] *= al0; o[nt][1] *= al0;
            o[nt][2] *= al1; o[nt][3] *= al1;
        }

        #pragma unroll
        for (int kv = 0; kv < 4; kv++) {
            uint32_t pa[4];
            pa[0] = pack_h2(s[2 * kv][0],     s[2 * kv][1]);
            pa[1] = pack_h2(s[2 * kv][2],     s[2 * kv][3]);
            pa[2] = pack_h2(s[2 * kv + 1][0], s[2 * kv + 1][1]);
            pa[3] = pack_h2(s[2 * kv + 1][2], s[2 * kv + 1][3]);
            uint32_t bf[8][2];
            #pragma unroll
            for (int p = 0; p < 4; p++) {
                uint32_t r4[4];
                ldm_x4_t(r4, sv + (t_off + (uint32_t)(kv * 16) * APAD + p * 16) * 2);
                bf[2 * p][0]     = r4[0];
                bf[2 * p][1]     = r4[1];
                bf[2 * p + 1][0] = r4[2];
                bf[2 * p + 1][1] = r4[3];
            }
            #pragma unroll
            for (int nt = 0; nt < 8; nt++)
                mma_f16(o[nt], pa, bf[nt]);
        }
    }

    const int g = lane >> 2;
    const int row0 = wid * 16 + g;
    float* po = g_pO + ((size_t)(bh * NSPLIT + sp) * N2) * DH;
    #pragma unroll
    for (int nt = 0; nt < 8; nt++) {
        *reinterpret_cast<float2*>(po + (size_t)row0 * DH + nt * 8 + 2 * tg) =
            make_float2(o[nt][0], o[nt][1]);
        *reinterpret_cast<float2*>(po + (size_t)(row0 + 8) * DH + nt * 8 + 2 * tg) =
            make_float2(o[nt][2], o[nt][3]);
    }
    if (tg == 0) {
        float* pml = g_pml + (size_t)(bh * NSPLIT + sp) * 2 * N2;
        pml[row0]          = m0r;
        pml[row0 + 8]      = m1r;
        pml[N2 + row0]     = l0r;
        pml[N2 + row0 + 8] = l1r;
    }
}

// ---------------------------------------------------------------------------
// Merge partials -> g_attnh (half)
// ---------------------------------------------------------------------------
__global__ __launch_bounds__(256) void attn_merge()
{
    const int bh = blockIdx.x;
    const int b = bh / HEADS;
    const int h = bh - b * HEADS;
    const int tid = threadIdx.x;
    const int q  = tid >> 2;
    const int dq = tid & 3;

    float ms[NSPLIT], ls[NSPLIT];
    float M = -1e30f;
    #pragma unroll
    for (int s = 0; s < NSPLIT; s++) {
        const float* pml = g_pml + (size_t)(bh * NSPLIT + s) * 2 * N2;
        ms[s] = pml[q];
        ls[s] = pml[N2 + q];
        M = fmaxf(M, ms[s]);
    }
    float w[NSPLIT], lt = 0.f;
    #pragma unroll
    for (int s = 0; s < NSPLIT; s++) {
        w[s] = __expf(ms[s] - M);
        lt += ls[s] * w[s];
    }
    const float inv = 1.0f / lt;

    __half* dst = g_attnh + ((size_t)(b * N2 + q)) * DIM + h * DH + dq * 16;
    #pragma unroll
    for (int j = 0; j < 4; j++) {
        float4 acc = make_float4(0.f, 0.f, 0.f, 0.f);
        #pragma unroll
        for (int s = 0; s < NSPLIT; s++) {
            const float4 v = *reinterpret_cast<const float4*>(
                g_pO + ((size_t)(bh * NSPLIT + s) * N2 + q) * DH + dq * 16 + j * 4);
            acc.x += w[s] * v.x;
            acc.y += w[s] * v.y;
            acc.z += w[s] * v.z;
            acc.w += w[s] * v.w;
        }
        __half2 h0 = make_half2(__float2half_rn(acc.x * inv), __float2half_rn(acc.y * inv));
        __half2 h1 = make_half2(__float2half_rn(acc.z * inv), __float2half_rn(acc.w * inv));
        *reinterpret_cast<__half2*>(dst + j * 4)     = h0;
        *reinterpret_cast<__half2*>(dst + j * 4 + 2) = h1;
    }
}

// ---------------------------------------------------------------------------
// Launch (multi-stream fork/join, graph-capture safe)
// ---------------------------------------------------------------------------
extern "C" void kernel_launch(void* const* d_in, const int* in_sizes, int n_in,
                              void* d_out, int out_size)
{
    const float* x       = (const float*)d_in[0];
    const float* latents = (const float*)d_in[1];
    const float* mask    = (const float*)d_in[2];
    const float* ln1g    = (const float*)d_in[3];
    const float* ln1b    = (const float*)d_in[4];
    const float* ln2g    = (const float*)d_in[5];
    const float* ln2b    = (const float*)d_in[6];
    const float* Wq      = (const float*)d_in[7];
    const float* Wkv     = (const float*)d_in[8];
    const float* Wout    = (const float*)d_in[9];
    float* out = (float*)d_out;

    __half *p_kvin, *p_lnh, *p_qh, *p_kvh, *p_attnh, *p_wkvT, *p_wqT, *p_woT;
    cudaGetSymbolAddress((void**)&p_kvin,  g_kvin);
    cudaGetSymbolAddress((void**)&p_lnh,   g_lnh);
    cudaGetSymbolAddress((void**)&p_qh,    g_qh);
    cudaGetSymbolAddress((void**)&p_kvh,   g_kvh);
    cudaGetSymbolAddress((void**)&p_attnh, g_attnh);
    cudaGetSymbolAddress((void**)&p_wkvT,  g_wkvT);
    cudaGetSymbolAddress((void**)&p_wqT,   g_wqT);
    cudaGetSymbolAddress((void**)&p_woT,   g_woT);

    static bool init_done = false;
    static cudaStream_t s1, s2;
    static cudaEvent_t evRoot, evWkv, evLN, evQ;
    if (!init_done) {
        cudaFuncSetAttribute(gemm_tc<__half>, cudaFuncAttributeMaxDynamicSharedMemorySize,
                             GEMM_SMEM_BYTES);
        cudaFuncSetAttribute(gemm_tc_s<__half>, cudaFuncAttributeMaxDynamicSharedMemorySize,
                             GEMM_S_SMEM_BYTES);
        cudaFuncSetAttribute(gemm_tc_s<float>, cudaFuncAttributeMaxDynamicSharedMemorySize,
                             GEMM_S_SMEM_BYTES);
        cudaStreamCreateWithFlags(&s1, cudaStreamNonBlocking);
        cudaStreamCreateWithFlags(&s2, cudaStreamNonBlocking);
        cudaEventCreateWithFlags(&evRoot, cudaEventDisableTiming);
        cudaEventCreateWithFlags(&evWkv,  cudaEventDisableTiming);
        cudaEventCreateWithFlags(&evLN,   cudaEventDisableTiming);
        cudaEventCreateWithFlags(&evQ,    cudaEventDisableTiming);
        init_done = true;
    }

    // Fork side streams from the main (capture) stream
    cudaEventRecord(evRoot, 0);
    cudaStreamWaitEvent(s1, evRoot, 0);
    cudaStreamWaitEvent(s2, evRoot, 0);

    // s1: Wkv transpose (needed by KV GEMM)
    transpose_kernel<<<dim3(2 * DIM / 32, DIM / 32), dim3(32, 8), 0, s1>>>(Wkv, p_wkvT, 2 * DIM);
    cudaEventRecord(evWkv, s1);

    // s2: Wq + Wout transposes, then (after LN) Q GEMM
    transpose_kernel<<<dim3(DIM / 32, DIM / 32), dim3(32, 8), 0, s2>>>(Wq, p_wqT, DIM);
    transpose_kernel<<<dim3(DIM / 32, DIM / 32), dim3(32, 8), 0, s2>>>(Wout, p_woT, DIM);

    // main: LayerNorms
    ln_kernel<<<MROWS / 2, 256>>>(x, latents, ln1g, ln1b, ln2g, ln2b);
    cudaEventRecord(evLN, 0);

    // s2: Q GEMM (needs LN + wqT)
    cudaStreamWaitEvent(s2, evLN, 0);
    gemm_tc_s<__half><<<dim3(DIM / 64, BATCH * N2 / 64), 256, GEMM_S_SMEM_BYTES, s2>>>(
        p_lnh, p_wqT, p_qh, DIM);
    cudaEventRecord(evQ, s2);

    // main: KV GEMM (needs LN on this stream + wkvT from s1)
    cudaStreamWaitEvent(0, evWkv, 0);
    gemm_tc<__half><<<dim3(2 * DIM / 128, MROWS / 128), 256, GEMM_SMEM_BYTES>>>(
        p_kvin, p_wkvT, p_kvh, 2 * DIM);

    // main: attention (needs KV here + Q from s2), merge, Out GEMM (woT joined via evQ)
    cudaStreamWaitEvent(0, evQ, 0);
    attn_partial<<<dim3(HEADS, BATCH, NSPLIT), 128>>>(mask);
    attn_merge<<<BATCH * HEADS, 256>>>();
    gemm_tc_s<float><<<dim3(DIM / 64, BATCH * N2 / 64), 256, GEMM_S_SMEM_BYTES>>>(
        p_attnh, p_woT, out, DIM);
}

// round 13
// speedup vs baseline: 1.5120x; 1.5120x over previous
#include <cuda_runtime.h>
#include <cuda_fp16.h>
#include <cstdint>

// ---------------------------------------------------------------------------
// PerceiverAttention, sm_103 — Round 12:
//   * full revert to the 545us base (single stream, R9 gemm_tc / attn)
//   * ln_kernel: 4 rows/block, 64 thr/row, 4x float4 per thread (MLP=4)
//   * Wq/Wout transposes fused into one launch (grid.z)
// ---------------------------------------------------------------------------

#define BATCH 8
#define N1 4096
#define N2 64
#define NKEYS 4160
#define DIM 1024
#define HEADS 16
#define DH 64
#define MROWS (BATCH * NKEYS)   // 33280
#define NSPLIT 5
#define CH_PER_SPLIT 13

__device__ __half g_kvin[(size_t)MROWS * DIM];
__device__ __half g_lnh [(size_t)BATCH * N2 * DIM];
__device__ __half g_qh  [(size_t)BATCH * N2 * DIM];
__device__ __half g_kvh [(size_t)MROWS * 2 * DIM];
__device__ __half g_attnh[(size_t)BATCH * N2 * DIM];
__device__ __half g_wkvT[(size_t)2 * DIM * DIM];
__device__ __half g_wqT [(size_t)DIM * DIM];
__device__ __half g_woT [(size_t)DIM * DIM];
__device__ float  g_pO  [(size_t)BATCH * HEADS * NSPLIT * N2 * DH];
__device__ float  g_pml [(size_t)BATCH * HEADS * NSPLIT * 2 * N2];

// ---------------------------------------------------------------------------
// Helpers
// ---------------------------------------------------------------------------
__device__ __forceinline__ uint32_t smem_u32(const void* p) {
    uint32_t a;
    asm("{ .reg .u64 t; cvta.to.shared.u64 t, %1; cvt.u32.u64 %0, t; }" : "=r"(a) : "l"(p));
    return a;
}
__device__ __forceinline__ void cp_async16(uint32_t dst, const void* src) {
    asm volatile("cp.async.cg.shared.global [%0], [%1], 16;" :: "r"(dst), "l"(src));
}
__device__ __forceinline__ void cp_commit() {
    asm volatile("cp.async.commit_group;" ::: "memory");
}
template <int N>
__device__ __forceinline__ void cp_wait() {
    asm volatile("cp.async.wait_group %0;" :: "n"(N) : "memory");
}
__device__ __forceinline__ void mma_f16(float* d, const uint32_t* a, const uint32_t* b) {
    asm volatile(
        "mma.sync.aligned.m16n8k16.row.col.f32.f16.f16.f32 "
        "{%0,%1,%2,%3}, {%4,%5,%6,%7}, {%8,%9}, {%0,%1,%2,%3};"
        : "+f"(d[0]), "+f"(d[1]), "+f"(d[2]), "+f"(d[3])
        : "r"(a[0]), "r"(a[1]), "r"(a[2]), "r"(a[3]), "r"(b[0]), "r"(b[1]));
}
__device__ __forceinline__ void ldm_x4(uint32_t* r, uint32_t addr) {
    asm volatile("ldmatrix.sync.aligned.m8n8.x4.shared.b16 {%0,%1,%2,%3}, [%4];"
        : "=r"(r[0]), "=r"(r[1]), "=r"(r[2]), "=r"(r[3]) : "r"(addr));
}
__device__ __forceinline__ void ldm_x4_t(uint32_t* r, uint32_t addr) {
    asm volatile("ldmatrix.sync.aligned.m8n8.x4.trans.shared.b16 {%0,%1,%2,%3}, [%4];"
        : "=r"(r[0]), "=r"(r[1]), "=r"(r[2]), "=r"(r[3]) : "r"(addr));
}
__device__ __forceinline__ uint32_t pack_h2(float a, float b) {
    __half2 h = __floats2half2_rn(a, b);
    return *reinterpret_cast<uint32_t*>(&h);
}
__device__ __forceinline__ void store_pair(float* p, float a, float b) {
    *reinterpret_cast<float2*>(p) = make_float2(a, b);
}
__device__ __forceinline__ void store_pair(__half* p, float a, float b) {
    *reinterpret_cast<__half2*>(p) = make_half2(__float2half_rn(a), __float2half_rn(b));
}

// ---------------------------------------------------------------------------
// Weight transpose + fp16 round (single matrix)
// ---------------------------------------------------------------------------
__global__ __launch_bounds__(256) void transpose_kernel(
    const float* __restrict__ in, __half* __restrict__ out, int ncols)
{
    __shared__ float t[32][33];
    const int bx = blockIdx.x * 32;
    const int by = blockIdx.y * 32;
    const int x = threadIdx.x;
    const int y = threadIdx.y;
    #pragma unroll
    for (int i = 0; i < 32; i += 8)
        t[y + i][x] = in[(size_t)(by + y + i) * ncols + bx + x];
    __syncthreads();
    #pragma unroll
    for (int i = 0; i < 32; i += 8)
        out[(size_t)(bx + y + i) * DIM + by + x] = __float2half_rn(t[x][y + i]);
}

// Fused transpose for Wq (z=0) and Wout (z=1), both DIM x DIM
__global__ __launch_bounds__(256) void transpose2_kernel(
    const float* __restrict__ inq, const float* __restrict__ ino,
    __half* __restrict__ outq, __half* __restrict__ outo)
{
    __shared__ float t[32][33];
    const float* in  = blockIdx.z ? ino  : inq;
    __half*      out = blockIdx.z ? outo : outq;
    const int bx = blockIdx.x * 32;
    const int by = blockIdx.y * 32;
    const int x = threadIdx.x;
    const int y = threadIdx.y;
    #pragma unroll
    for (int i = 0; i < 32; i += 8)
        t[y + i][x] = in[(size_t)(by + y + i) * DIM + bx + x];
    __syncthreads();
    #pragma unroll
    for (int i = 0; i < 32; i += 8)
        out[(size_t)(bx + y + i) * DIM + by + x] = __float2half_rn(t[x][y + i]);
}

// ---------------------------------------------------------------------------
// LayerNorm -> half outputs. 4 rows/block, 64 threads/row, 4x float4/thread.
// ---------------------------------------------------------------------------
__global__ __launch_bounds__(256) void ln_kernel(
    const float* __restrict__ x, const float* __restrict__ lat,
    const float* __restrict__ g1, const float* __restrict__ b1,
    const float* __restrict__ g2, const float* __restrict__ b2)
{
    __shared__ float red[16];            // [8 warps][{s,sq}]
    const int rid  = threadIdx.x >> 6;   // row within block (0..3)
    const int tl   = threadIdx.x & 63;
    const int wid  = threadIdx.x >> 5;   // 0..7
    const int lane = threadIdx.x & 31;

    const int r  = blockIdx.x * 4 + rid;
    const int bb = r / NKEYS;
    const int i  = r - bb * NKEYS;

    const float* src;
    const float* g;
    const float* be;
    __half* dst2 = nullptr;
    if (i < N1) {
        src = x + ((size_t)bb * N1 + i) * DIM;
        g = g1; be = b1;
    } else {
        const int j = i - N1;
        src = lat + ((size_t)bb * N2 + j) * DIM;
        g = g2; be = b2;
        dst2 = g_lnh + ((size_t)bb * N2 + j) * DIM;
    }
    __half* dst = g_kvin + (size_t)r * DIM;

    const float4* s4 = reinterpret_cast<const float4*>(src);
    float4 v[4];
    #pragma unroll
    for (int p = 0; p < 4; p++) v[p] = s4[tl + 64 * p];

    float s = 0.f, sq = 0.f;
    #pragma unroll
    for (int p = 0; p < 4; p++) {
        s  += v[p].x + v[p].y + v[p].z + v[p].w;
        sq += v[p].x*v[p].x + v[p].y*v[p].y + v[p].z*v[p].z + v[p].w*v[p].w;
    }
    #pragma unroll
    for (int o = 16; o > 0; o >>= 1) {
        s  += __shfl_xor_sync(0xffffffffu, s, o);
        sq += __shfl_xor_sync(0xffffffffu, sq, o);
    }
    if (lane == 0) { red[wid * 2] = s; red[wid * 2 + 1] = sq; }
    __syncthreads();
    const float S  = red[rid * 4]     + red[rid * 4 + 2];
    const float SQ = red[rid * 4 + 1] + red[rid * 4 + 3];

    const float mu   = S * (1.0f / DIM);
    const float var  = SQ * (1.0f / DIM) - mu * mu;
    const float rstd = rsqrtf(var + 1e-5f);

    const float4* g4 = reinterpret_cast<const float4*>(g);
    const float4* b4 = reinterpret_cast<const float4*>(be);
    #pragma unroll
    for (int p = 0; p < 4; p++) {
        const float4 gv = g4[tl + 64 * p];
        const float4 bv = b4[tl + 64 * p];
        uint2 u;
        __half2* hp = reinterpret_cast<__half2*>(&u);
        hp[0] = make_half2(__float2half_rn((v[p].x - mu) * rstd * gv.x + bv.x),
                           __float2half_rn((v[p].y - mu) * rstd * gv.y + bv.y));
        hp[1] = make_half2(__float2half_rn((v[p].z - mu) * rstd * gv.z + bv.z),
                           __float2half_rn((v[p].w - mu) * rstd * gv.w + bv.w));
        reinterpret_cast<uint2*>(dst)[tl + 64 * p] = u;
        if (dst2) reinterpret_cast<uint2*>(dst2)[tl + 64 * p] = u;
    }
}

// ---------------------------------------------------------------------------
// fp16 mma.sync GEMM (128x128 tile) — known-good config
// ---------------------------------------------------------------------------
#define PADH 72
#define TILE_H (128 * PADH)
#define NSTAGE 3
#define GEMM_SMEM_BYTES (NSTAGE * 2 * TILE_H * 2)   // 110592

template <typename OutT>
__global__ __launch_bounds__(256, 2) void gemm_tc(
    const __half* __restrict__ A, const __half* __restrict__ Bt,
    OutT* __restrict__ C, int ldc)
{
    extern __shared__ __half smh[];
    const uint32_t sb = smem_u32(smh);

    const int tid  = threadIdx.x;
    const int wid  = tid >> 5;
    const int lane = tid & 31;
    const int wm = wid & 3;
    const int wn = wid >> 2;
    const int m0 = blockIdx.y * 128;
    const int n0 = blockIdx.x * 128;

    const __half* ga = A  + (size_t)m0 * DIM;
    const __half* gb = Bt + (size_t)n0 * DIM;

    const int lr = tid >> 3;
    const int lc = tid & 7;

    float acc[2][8][4];
    #pragma unroll
    for (int i = 0; i < 2; i++)
        #pragma unroll
        for (int j = 0; j < 8; j++)
            #pragma unroll
            for (int q = 0; q < 4; q++) acc[i][j][q] = 0.f;

    const uint32_t a_off = (uint32_t)(wm * 32 + (lane & 15)) * PADH + (lane >> 4) * 8;
    const uint32_t b_off = (uint32_t)(wn * 64 + ((lane >> 4) << 3) + (lane & 7)) * PADH
                         + ((lane >> 3) & 1) * 8;

    auto load_tile = [&](int chunk, int stage) {
        const uint32_t abase = sb + (uint32_t)stage * 2 * TILE_H * 2;
        const uint32_t bbase = abase + TILE_H * 2;
        const int k0 = chunk * 64;
        #pragma unroll
        for (int i = 0; i < 4; i++) {
            const int r = lr + i * 32;
            cp_async16(abase + (r * PADH + lc * 8) * 2, ga + (size_t)r * DIM + k0 + lc * 8);
        }
        #pragma unroll
        for (int i = 0; i < 4; i++) {
            const int r = lr + i * 32;
            cp_async16(bbase + (r * PADH + lc * 8) * 2, gb + (size_t)r * DIM + k0 + lc * 8);
        }
        cp_commit();
    };

    const int NCHUNK = DIM / 64;   // 16
    load_tile(0, 0);
    load_tile(1, 1);

    for (int c = 0; c < NCHUNK; c++) {
        const int stage = c % NSTAGE;
        if (c + 2 < NCHUNK) { load_tile(c + 2, (c + 2) % NSTAGE); cp_wait<1>(); }
        else                { cp_wait<0>(); }
        __syncthreads();

        const uint32_t sA = sb + (uint32_t)stage * 2 * TILE_H * 2;
        const uint32_t sB = sA + TILE_H * 2;

        #pragma unroll
        for (int kk = 0; kk < 4; kk++) {
            uint32_t af[2][4], bf[8][2];
            #pragma unroll
            for (int mt = 0; mt < 2; mt++)
                ldm_x4(af[mt], sA + (a_off + (uint32_t)(mt * 16) * PADH + kk * 16) * 2);
            #pragma unroll
            for (int p = 0; p < 4; p++) {
                uint32_t r4[4];
                ldm_x4(r4, sB + (b_off + (uint32_t)(p * 16) * PADH + kk * 16) * 2);
                bf[2 * p][0]     = r4[0];
                bf[2 * p][1]     = r4[1];
                bf[2 * p + 1][0] = r4[2];
                bf[2 * p + 1][1] = r4[3];
            }
            #pragma unroll
            for (int mt = 0; mt < 2; mt++)
                #pragma unroll
                for (int nt = 0; nt < 8; nt++)
                    mma_f16(acc[mt][nt], af[mt], bf[nt]);
        }
        __syncthreads();
    }

    #pragma unroll
    for (int mt = 0; mt < 2; mt++) {
        const int row = m0 + wm * 32 + mt * 16 + (lane >> 2);
        #pragma unroll
        for (int nt = 0; nt < 8; nt++) {
            const int col = n0 + wn * 64 + nt * 8 + (lane & 3) * 2;
            store_pair(C + (size_t)row * ldc + col, acc[mt][nt][0], acc[mt][nt][1]);
            store_pair(C + (size_t)(row + 8) * ldc + col, acc[mt][nt][2], acc[mt][nt][3]);
        }
    }
}

// ---------------------------------------------------------------------------
// Small-tile fp16 GEMM (64x64 CTA tile) for 512-row GEMMs
// ---------------------------------------------------------------------------
#define TILE_HS (64 * PADH)
#define GEMM_S_SMEM_BYTES (NSTAGE * 2 * TILE_HS * 2)   // 55296

template <typename OutT>
__global__ __launch_bounds__(256, 2) void gemm_tc_s(
    const __half* __restrict__ A, const __half* __restrict__ Bt,
    OutT* __restrict__ C, int ldc)
{
    extern __shared__ __half smh[];
    const uint32_t sb = smem_u32(smh);

    const int tid  = threadIdx.x;
    const int wid  = tid >> 5;
    const int lane = tid & 31;
    const int wm = wid & 3;
    const int wn = wid >> 2;
    const int m0 = blockIdx.y * 64;
    const int n0 = blockIdx.x * 64;

    const __half* ga = A  + (size_t)m0 * DIM;
    const __half* gb = Bt + (size_t)n0 * DIM;

    const int lr = tid >> 3;
    const int lc = tid & 7;

    float acc[4][4];
    #pragma unroll
    for (int j = 0; j < 4; j++)
        #pragma unroll
        for (int q = 0; q < 4; q++) acc[j][q] = 0.f;

    const uint32_t a_off = (uint32_t)(wm * 16 + (lane & 15)) * PADH + (lane >> 4) * 8;
    const uint32_t b_off = (uint32_t)(wn * 32 + ((lane >> 4) << 3) + (lane & 7)) * PADH
                         + ((lane >> 3) & 1) * 8;

    auto load_tile = [&](int chunk, int stage) {
        const uint32_t abase = sb + (uint32_t)stage * 2 * TILE_HS * 2;
        const uint32_t bbase = abase + TILE_HS * 2;
        const int k0 = chunk * 64;
        #pragma unroll
        for (int i = 0; i < 2; i++) {
            const int r = lr + i * 32;
            cp_async16(abase + (r * PADH + lc * 8) * 2, ga + (size_t)r * DIM + k0 + lc * 8);
        }
        #pragma unroll
        for (int i = 0; i < 2; i++) {
            const int r = lr + i * 32;
            cp_async16(bbase + (r * PADH + lc * 8) * 2, gb + (size_t)r * DIM + k0 + lc * 8);
        }
        cp_commit();
    };

    const int NCHUNK = DIM / 64;
    load_tile(0, 0);
    load_tile(1, 1);

    for (int c = 0; c < NCHUNK; c++) {
        const int stage = c % NSTAGE;
        if (c + 2 < NCHUNK) { load_tile(c + 2, (c + 2) % NSTAGE); cp_wait<1>(); }
        else                { cp_wait<0>(); }
        __syncthreads();

        const uint32_t sA = sb + (uint32_t)stage * 2 * TILE_HS * 2;
        const uint32_t sB = sA + TILE_HS * 2;

        #pragma unroll
        for (int kk = 0; kk < 4; kk++) {
            uint32_t af[4], bf[4][2];
            ldm_x4(af, sA + (a_off + kk * 16) * 2);
            #pragma unroll
            for (int p = 0; p < 2; p++) {
                uint32_t r4[4];
                ldm_x4(r4, sB + (b_off + (uint32_t)(p * 16) * PADH + kk * 16) * 2);
                bf[2 * p][0]     = r4[0];
                bf[2 * p][1]     = r4[1];
                bf[2 * p + 1][0] = r4[2];
                bf[2 * p + 1][1] = r4[3];
            }
            #pragma unroll
            for (int nt = 0; nt < 4; nt++)
                mma_f16(acc[nt], af, bf[nt]);
        }
        __syncthreads();
    }

    const int row = m0 + wm * 16 + (lane >> 2);
    #pragma unroll
    for (int nt = 0; nt < 4; nt++) {
        const int col = n0 + wn * 32 + nt * 8 + (lane & 3) * 2;
        store_pair(C + (size_t)row * ldc + col, acc[nt][0], acc[nt][1]);
        store_pair(C + (size_t)(row + 8) * ldc + col, acc[nt][2], acc[nt][3]);
    }
}

// ---------------------------------------------------------------------------
// Split-K flash attention on fp16 mma.sync (unchanged, known good)
// ---------------------------------------------------------------------------
#define APAD 72

__global__ __launch_bounds__(128) void attn_partial(const float* __restrict__ mask)
{
    __shared__ __half qs [64 * APAD];
    __shared__ __half ks [64 * APAD];
    __shared__ __half vsk[64 * APAD];
    __shared__ float bias[64];

    const int h = blockIdx.x;
    const int b = blockIdx.y;
    const int sp = blockIdx.z;
    const int bh = b * HEADS + h;
    const int tid = threadIdx.x;
    const int wid = tid >> 5;
    const int lane = tid & 31;
    const uint32_t sq = smem_u32(qs);
    const uint32_t sk = smem_u32(ks);
    const uint32_t sv = smem_u32(vsk);

    {
        const int q = tid >> 1;
        const int d0 = (tid & 1) * 32;
        const uint4* src = reinterpret_cast<const uint4*>(
            g_qh + (size_t)(b * N2 + q) * DIM + h * DH + d0);
        const __half2 s2 = __half2half2(__float2half(0.125f));
        #pragma unroll
        for (int i = 0; i < 4; i++) {
            uint4 u = src[i];
            __half2* hp = reinterpret_cast<__half2*>(&u);
            #pragma unroll
            for (int j = 0; j < 4; j++) hp[j] = __hmul2(hp[j], s2);
            *reinterpret_cast<uint4*>(qs + q * APAD + d0 + i * 8) = u;
        }
    }

    float o[8][4];
    #pragma unroll
    for (int j = 0; j < 8; j++)
        #pragma unroll
        for (int q = 0; q < 4; q++) o[j][q] = 0.f;
    float m0r = -1e30f, m1r = -1e30f, l0r = 0.f, l1r = 0.f;

    const uint32_t a_off = (uint32_t)(wid * 16 + (lane & 15)) * APAD + (lane >> 4) * 8;
    const uint32_t b_off = (uint32_t)(((lane >> 4) << 3) + (lane & 7)) * APAD
                         + ((lane >> 3) & 1) * 8;
    const uint32_t t_off = (uint32_t)(((lane >> 3) & 1) * 8 + (lane & 7)) * APAD
                         + (lane >> 4) * 8;
    const int tg = lane & 3;

    for (int cc = 0; cc < CH_PER_SPLIT; cc++) {
        const int key0 = (sp * CH_PER_SPLIT + cc) * 64;
        __syncthreads();

        {
            const int row = tid >> 1;
            const int cb = (tid & 1) * 4;
            const __half* ksrc = g_kvh + ((size_t)(b * NKEYS) + key0 + row) * (2 * DIM) + h * DH;
            const __half* vsrc = ksrc + DIM;
            #pragma unroll
            for (int i = 0; i < 4; i++)
                cp_async16(sk + (row * APAD + (cb + i) * 8) * 2, ksrc + (cb + i) * 8);
            #pragma unroll
            for (int i = 0; i < 4; i++)
                cp_async16(sv + (row * APAD + (cb + i) * 8) * 2, vsrc + (cb + i) * 8);
            cp_commit();
        }
        if (tid < 64) {
            const int kg = key0 + tid;
            bias[tid] = (kg < N1) ? (mask[(size_t)b * N1 + kg] - 1.0f) * 100.0f : 0.f;
        }
        cp_wait<0>();
        __syncthreads();

        float s[8][4];
        #pragma unroll
        for (int j = 0; j < 8; j++)
            #pragma unroll
            for (int q = 0; q < 4; q++) s[j][q] = 0.f;
        #pragma unroll
        for (int kk = 0; kk < 4; kk++) {
            uint32_t af[4], bf[8][2];
            ldm_x4(af, sq + (a_off + kk * 16) * 2);
            #pragma unroll
            for (int p = 0; p < 4; p++) {
                uint32_t r4[4];
                ldm_x4(r4, sk + (b_off + (uint32_t)(p * 16) * APAD + kk * 16) * 2);
                bf[2 * p][0]     = r4[0];
                bf[2 * p][1]     = r4[1];
                bf[2 * p + 1][0] = r4[2];
                bf[2 * p + 1][1] = r4[3];
            }
            #pragma unroll
            for (int nt = 0; nt < 8; nt++)
                mma_f16(s[nt], af, bf[nt]);
        }

        float c0 = -1e30f, c1 = -1e30f;
        #pragma unroll
        for (int nt = 0; nt < 8; nt++) {
            const float b0 = bias[nt * 8 + 2 * tg];
            const float b1 = bias[nt * 8 + 2 * tg + 1];
            s[nt][0] += b0; s[nt][1] += b1; s[nt][2] += b0; s[nt][3] += b1;
            c0 = fmaxf(c0, fmaxf(s[nt][0], s[nt][1]));
            c1 = fmaxf(c1, fmaxf(s[nt][2], s[nt][3]));
        }
        c0 = fmaxf(c0, __shfl_xor_sync(0xffffffffu, c0, 1));
        c0 = fmaxf(c0, __shfl_xor_sync(0xffffffffu, c0, 2));
        c1 = fmaxf(c1, __shfl_xor_sync(0xffffffffu, c1, 1));
        c1 = fmaxf(c1, __shfl_xor_sync(0xffffffffu, c1, 2));

        const float mn0 = fmaxf(m0r, c0);
        const float mn1 = fmaxf(m1r, c1);
        const float al0 = __expf(m0r - mn0);
        const float al1 = __expf(m1r - mn1);
        float cs0 = 0.f, cs1 = 0.f;
        #pragma unroll
        for (int nt = 0; nt < 8; nt++) {
            s[nt][0] = __expf(s[nt][0] - mn0); cs0 += s[nt][0];
            s[nt][1] = __expf(s[nt][1] - mn0); cs0 += s[nt][1];
            s[nt][2] = __expf(s[nt][2] - mn1); cs1 += s[nt][2];
            s[nt][3] = __expf(s[nt][3] - mn1); cs1 += s[nt][3];
        }
        cs0 += __shfl_xor_sync(0xffffffffu, cs0, 1);
        cs0 += __shfl_xor_sync(0xffffffffu, cs0, 2);
        cs1 += __shfl_xor_sync(0xffffffffu, cs1, 1);
        cs1 += __shfl_xor_sync(0xffffffffu, cs1, 2);
        l0r = l0r * al0 + cs0; m0r = mn0;
        l1r = l1r * al1 + cs1; m1r = mn1;
        #pragma unroll
        for (int nt = 0; nt < 8; nt++) {
            o[nt][0] *= al0; o[nt][1] *= al0;
            o[nt][2] *= al1; o[nt][3] *= al1;
        }

        #pragma unroll
        for (int kv = 0; kv < 4; kv++) {
            uint32_t pa[4];
            pa[0] = pack_h2(s[2 * kv][0],     s[2 * kv][1]);
            pa[1] = pack_h2(s[2 * kv][2],     s[2 * kv][3]);
            pa[2] = pack_h2(s[2 * kv + 1][0], s[2 * kv + 1][1]);
            pa[3] = pack_h2(s[2 * kv + 1][2], s[2 * kv + 1][3]);
            uint32_t bf[8][2];
            #pragma unroll
            for (int p = 0; p < 4; p++) {
                uint32_t r4[4];
                ldm_x4_t(r4, sv + (t_off + (uint32_t)(kv * 16) * APAD + p * 16) * 2);
                bf[2 * p][0]     = r4[0];
                bf[2 * p][1]     = r4[1];
                bf[2 * p + 1][0] = r4[2];
                bf[2 * p + 1][1] = r4[3];
            }
            #pragma unroll
            for (int nt = 0; nt < 8; nt++)
                mma_f16(o[nt], pa, bf[nt]);
        }
    }

    const int g = lane >> 2;
    const int row0 = wid * 16 + g;
    float* po = g_pO + ((size_t)(bh * NSPLIT + sp) * N2) * DH;
    #pragma unroll
    for (int nt = 0; nt < 8; nt++) {
        *reinterpret_cast<float2*>(po + (size_t)row0 * DH + nt * 8 + 2 * tg) =
            make_float2(o[nt][0], o[nt][1]);
        *reinterpret_cast<float2*>(po + (size_t)(row0 + 8) * DH + nt * 8 + 2 * tg) =
            make_float2(o[nt][2], o[nt][3]);
    }
    if (tg == 0) {
        float* pml = g_pml + (size_t)(bh * NSPLIT + sp) * 2 * N2;
        pml[row0]          = m0r;
        pml[row0 + 8]      = m1r;
        pml[N2 + row0]     = l0r;
        pml[N2 + row0 + 8] = l1r;
    }
}

// ---------------------------------------------------------------------------
// Merge partials -> g_attnh (half)
// ---------------------------------------------------------------------------
__global__ __launch_bounds__(256) void attn_merge()
{
    const int bh = blockIdx.x;
    const int b = bh / HEADS;
    const int h = bh - b * HEADS;
    const int tid = threadIdx.x;
    const int q  = tid >> 2;
    const int dq = tid & 3;

    float ms[NSPLIT], ls[NSPLIT];
    float M = -1e30f;
    #pragma unroll
    for (int s = 0; s < NSPLIT; s++) {
        const float* pml = g_pml + (size_t)(bh * NSPLIT + s) * 2 * N2;
        ms[s] = pml[q];
        ls[s] = pml[N2 + q];
        M = fmaxf(M, ms[s]);
    }
    float w[NSPLIT], lt = 0.f;
    #pragma unroll
    for (int s = 0; s < NSPLIT; s++) {
        w[s] = __expf(ms[s] - M);
        lt += ls[s] * w[s];
    }
    const float inv = 1.0f / lt;

    __half* dst = g_attnh + ((size_t)(b * N2 + q)) * DIM + h * DH + dq * 16;
    #pragma unroll
    for (int j = 0; j < 4; j++) {
        float4 acc = make_float4(0.f, 0.f, 0.f, 0.f);
        #pragma unroll
        for (int s = 0; s < NSPLIT; s++) {
            const float4 v = *reinterpret_cast<const float4*>(
                g_pO + ((size_t)(bh * NSPLIT + s) * N2 + q) * DH + dq * 16 + j * 4);
            acc.x += w[s] * v.x;
            acc.y += w[s] * v.y;
            acc.z += w[s] * v.z;
            acc.w += w[s] * v.w;
        }
        __half2 h0 = make_half2(__float2half_rn(acc.x * inv), __float2half_rn(acc.y * inv));
        __half2 h1 = make_half2(__float2half_rn(acc.z * inv), __float2half_rn(acc.w * inv));
        *reinterpret_cast<__half2*>(dst + j * 4)     = h0;
        *reinterpret_cast<__half2*>(dst + j * 4 + 2) = h1;
    }
}

// ---------------------------------------------------------------------------
// Launch (single stream, serial — the proven schedule)
// ---------------------------------------------------------------------------
extern "C" void kernel_launch(void* const* d_in, const int* in_sizes, int n_in,
                              void* d_out, int out_size)
{
    const float* x       = (const float*)d_in[0];
    const float* latents = (const float*)d_in[1];
    const float* mask    = (const float*)d_in[2];
    const float* ln1g    = (const float*)d_in[3];
    const float* ln1b    = (const float*)d_in[4];
    const float* ln2g    = (const float*)d_in[5];
    const float* ln2b    = (const float*)d_in[6];
    const float* Wq      = (const float*)d_in[7];
    const float* Wkv     = (const float*)d_in[8];
    const float* Wout    = (const float*)d_in[9];
    float* out = (float*)d_out;

    __half *p_kvin, *p_lnh, *p_qh, *p_kvh, *p_attnh, *p_wkvT, *p_wqT, *p_woT;
    cudaGetSymbolAddress((void**)&p_kvin,  g_kvin);
    cudaGetSymbolAddress((void**)&p_lnh,   g_lnh);
    cudaGetSymbolAddress((void**)&p_qh,    g_qh);
    cudaGetSymbolAddress((void**)&p_kvh,   g_kvh);
    cudaGetSymbolAddress((void**)&p_attnh, g_attnh);
    cudaGetSymbolAddress((void**)&p_wkvT,  g_wkvT);
    cudaGetSymbolAddress((void**)&p_wqT,   g_wqT);
    cudaGetSymbolAddress((void**)&p_woT,   g_woT);

    static bool attr_set = false;
    if (!attr_set) {
        cudaFuncSetAttribute(gemm_tc<__half>, cudaFuncAttributeMaxDynamicSharedMemorySize,
                             GEMM_SMEM_BYTES);
        cudaFuncSetAttribute(gemm_tc_s<__half>, cudaFuncAttributeMaxDynamicSharedMemorySize,
                             GEMM_S_SMEM_BYTES);
        cudaFuncSetAttribute(gemm_tc_s<float>, cudaFuncAttributeMaxDynamicSharedMemorySize,
                             GEMM_S_SMEM_BYTES);
        attr_set = true;
    }

    // 0) Transpose + fp16-round weights (Wq+Wout fused, then Wkv)
    transpose2_kernel<<<dim3(DIM / 32, DIM / 32, 2), dim3(32, 8)>>>(Wq, Wout, p_wqT, p_woT);
    transpose_kernel<<<dim3(2 * DIM / 32, DIM / 32), dim3(32, 8)>>>(Wkv, p_wkvT, 2 * DIM);

    // 1) LayerNorms (half outputs; 4 rows per block)
    ln_kernel<<<MROWS / 4, 256>>>(x, latents, ln1g, ln1b, ln2g, ln2b);

    // 2) KV GEMM (fp16 mma, half output)
    gemm_tc<__half><<<dim3(2 * DIM / 128, MROWS / 128), 256, GEMM_SMEM_BYTES>>>(
        p_kvin, p_wkvT, p_kvh, 2 * DIM);

    // 3) Q GEMM (small tiles, half output)
    gemm_tc_s<__half><<<dim3(DIM / 64, BATCH * N2 / 64), 256, GEMM_S_SMEM_BYTES>>>(
        p_lnh, p_wqT, p_qh, DIM);

    // 4) Attention: fp16-MMA split-K partials + merge
    attn_partial<<<dim3(HEADS, BATCH, NSPLIT), 128>>>(mask);
    attn_merge<<<BATCH * HEADS, 256>>>();

    // 5) Out GEMM (small tiles, float output) -> d_out
    gemm_tc_s<float><<<dim3(DIM / 64, BATCH * N2 / 64), 256, GEMM_S_SMEM_BYTES>>>(
        p_attnh, p_woT, out, DIM);
}

// round 14
// speedup vs baseline: 1.5359x; 1.0158x over previous
#include <cuda_runtime.h>
#include <cuda_fp16.h>
#include <cstdint>

// ---------------------------------------------------------------------------
// PerceiverAttention, sm_103 — Round 13:
//   * gemm_tc: 128 threads/CTA, 4 warps of 64x64 (LDSM/MMA ratio 0.375->0.25),
//     same 128x128 CTA tile / 3-stage pipeline / 2 CTAs/SM, reg cap 256
// ---------------------------------------------------------------------------

#define BATCH 8
#define N1 4096
#define N2 64
#define NKEYS 4160
#define DIM 1024
#define HEADS 16
#define DH 64
#define MROWS (BATCH * NKEYS)   // 33280
#define NSPLIT 5
#define CH_PER_SPLIT 13

__device__ __half g_kvin[(size_t)MROWS * DIM];
__device__ __half g_lnh [(size_t)BATCH * N2 * DIM];
__device__ __half g_qh  [(size_t)BATCH * N2 * DIM];
__device__ __half g_kvh [(size_t)MROWS * 2 * DIM];
__device__ __half g_attnh[(size_t)BATCH * N2 * DIM];
__device__ __half g_wkvT[(size_t)2 * DIM * DIM];
__device__ __half g_wqT [(size_t)DIM * DIM];
__device__ __half g_woT [(size_t)DIM * DIM];
__device__ float  g_pO  [(size_t)BATCH * HEADS * NSPLIT * N2 * DH];
__device__ float  g_pml [(size_t)BATCH * HEADS * NSPLIT * 2 * N2];

// ---------------------------------------------------------------------------
// Helpers
// ---------------------------------------------------------------------------
__device__ __forceinline__ uint32_t smem_u32(const void* p) {
    uint32_t a;
    asm("{ .reg .u64 t; cvta.to.shared.u64 t, %1; cvt.u32.u64 %0, t; }" : "=r"(a) : "l"(p));
    return a;
}
__device__ __forceinline__ void cp_async16(uint32_t dst, const void* src) {
    asm volatile("cp.async.cg.shared.global [%0], [%1], 16;" :: "r"(dst), "l"(src));
}
__device__ __forceinline__ void cp_commit() {
    asm volatile("cp.async.commit_group;" ::: "memory");
}
template <int N>
__device__ __forceinline__ void cp_wait() {
    asm volatile("cp.async.wait_group %0;" :: "n"(N) : "memory");
}
__device__ __forceinline__ void mma_f16(float* d, const uint32_t* a, const uint32_t* b) {
    asm volatile(
        "mma.sync.aligned.m16n8k16.row.col.f32.f16.f16.f32 "
        "{%0,%1,%2,%3}, {%4,%5,%6,%7}, {%8,%9}, {%0,%1,%2,%3};"
        : "+f"(d[0]), "+f"(d[1]), "+f"(d[2]), "+f"(d[3])
        : "r"(a[0]), "r"(a[1]), "r"(a[2]), "r"(a[3]), "r"(b[0]), "r"(b[1]));
}
__device__ __forceinline__ void ldm_x4(uint32_t* r, uint32_t addr) {
    asm volatile("ldmatrix.sync.aligned.m8n8.x4.shared.b16 {%0,%1,%2,%3}, [%4];"
        : "=r"(r[0]), "=r"(r[1]), "=r"(r[2]), "=r"(r[3]) : "r"(addr));
}
__device__ __forceinline__ void ldm_x4_t(uint32_t* r, uint32_t addr) {
    asm volatile("ldmatrix.sync.aligned.m8n8.x4.trans.shared.b16 {%0,%1,%2,%3}, [%4];"
        : "=r"(r[0]), "=r"(r[1]), "=r"(r[2]), "=r"(r[3]) : "r"(addr));
}
__device__ __forceinline__ uint32_t pack_h2(float a, float b) {
    __half2 h = __floats2half2_rn(a, b);
    return *reinterpret_cast<uint32_t*>(&h);
}
__device__ __forceinline__ void store_pair(float* p, float a, float b) {
    *reinterpret_cast<float2*>(p) = make_float2(a, b);
}
__device__ __forceinline__ void store_pair(__half* p, float a, float b) {
    *reinterpret_cast<__half2*>(p) = make_half2(__float2half_rn(a), __float2half_rn(b));
}

// ---------------------------------------------------------------------------
// Weight transposes
// ---------------------------------------------------------------------------
__global__ __launch_bounds__(256) void transpose_kernel(
    const float* __restrict__ in, __half* __restrict__ out, int ncols)
{
    __shared__ float t[32][33];
    const int bx = blockIdx.x * 32;
    const int by = blockIdx.y * 32;
    const int x = threadIdx.x;
    const int y = threadIdx.y;
    #pragma unroll
    for (int i = 0; i < 32; i += 8)
        t[y + i][x] = in[(size_t)(by + y + i) * ncols + bx + x];
    __syncthreads();
    #pragma unroll
    for (int i = 0; i < 32; i += 8)
        out[(size_t)(bx + y + i) * DIM + by + x] = __float2half_rn(t[x][y + i]);
}

__global__ __launch_bounds__(256) void transpose2_kernel(
    const float* __restrict__ inq, const float* __restrict__ ino,
    __half* __restrict__ outq, __half* __restrict__ outo)
{
    __shared__ float t[32][33];
    const float* in  = blockIdx.z ? ino  : inq;
    __half*      out = blockIdx.z ? outo : outq;
    const int bx = blockIdx.x * 32;
    const int by = blockIdx.y * 32;
    const int x = threadIdx.x;
    const int y = threadIdx.y;
    #pragma unroll
    for (int i = 0; i < 32; i += 8)
        t[y + i][x] = in[(size_t)(by + y + i) * DIM + bx + x];
    __syncthreads();
    #pragma unroll
    for (int i = 0; i < 32; i += 8)
        out[(size_t)(bx + y + i) * DIM + by + x] = __float2half_rn(t[x][y + i]);
}

// ---------------------------------------------------------------------------
// LayerNorm -> half outputs. 4 rows/block, 64 threads/row (MLP=4).
// ---------------------------------------------------------------------------
__global__ __launch_bounds__(256) void ln_kernel(
    const float* __restrict__ x, const float* __restrict__ lat,
    const float* __restrict__ g1, const float* __restrict__ b1,
    const float* __restrict__ g2, const float* __restrict__ b2)
{
    __shared__ float red[16];
    const int rid  = threadIdx.x >> 6;
    const int tl   = threadIdx.x & 63;
    const int wid  = threadIdx.x >> 5;
    const int lane = threadIdx.x & 31;

    const int r  = blockIdx.x * 4 + rid;
    const int bb = r / NKEYS;
    const int i  = r - bb * NKEYS;

    const float* src;
    const float* g;
    const float* be;
    __half* dst2 = nullptr;
    if (i < N1) {
        src = x + ((size_t)bb * N1 + i) * DIM;
        g = g1; be = b1;
    } else {
        const int j = i - N1;
        src = lat + ((size_t)bb * N2 + j) * DIM;
        g = g2; be = b2;
        dst2 = g_lnh + ((size_t)bb * N2 + j) * DIM;
    }
    __half* dst = g_kvin + (size_t)r * DIM;

    const float4* s4 = reinterpret_cast<const float4*>(src);
    float4 v[4];
    #pragma unroll
    for (int p = 0; p < 4; p++) v[p] = s4[tl + 64 * p];

    float s = 0.f, sq = 0.f;
    #pragma unroll
    for (int p = 0; p < 4; p++) {
        s  += v[p].x + v[p].y + v[p].z + v[p].w;
        sq += v[p].x*v[p].x + v[p].y*v[p].y + v[p].z*v[p].z + v[p].w*v[p].w;
    }
    #pragma unroll
    for (int o = 16; o > 0; o >>= 1) {
        s  += __shfl_xor_sync(0xffffffffu, s, o);
        sq += __shfl_xor_sync(0xffffffffu, sq, o);
    }
    if (lane == 0) { red[wid * 2] = s; red[wid * 2 + 1] = sq; }
    __syncthreads();
    const float S  = red[rid * 4]     + red[rid * 4 + 2];
    const float SQ = red[rid * 4 + 1] + red[rid * 4 + 3];

    const float mu   = S * (1.0f / DIM);
    const float var  = SQ * (1.0f / DIM) - mu * mu;
    const float rstd = rsqrtf(var + 1e-5f);

    const float4* g4 = reinterpret_cast<const float4*>(g);
    const float4* b4 = reinterpret_cast<const float4*>(be);
    #pragma unroll
    for (int p = 0; p < 4; p++) {
        const float4 gv = g4[tl + 64 * p];
        const float4 bv = b4[tl + 64 * p];
        uint2 u;
        __half2* hp = reinterpret_cast<__half2*>(&u);
        hp[0] = make_half2(__float2half_rn((v[p].x - mu) * rstd * gv.x + bv.x),
                           __float2half_rn((v[p].y - mu) * rstd * gv.y + bv.y));
        hp[1] = make_half2(__float2half_rn((v[p].z - mu) * rstd * gv.z + bv.z),
                           __float2half_rn((v[p].w - mu) * rstd * gv.w + bv.w));
        reinterpret_cast<uint2*>(dst)[tl + 64 * p] = u;
        if (dst2) reinterpret_cast<uint2*>(dst2)[tl + 64 * p] = u;
    }
}

// ---------------------------------------------------------------------------
// fp16 mma.sync GEMM (128x128 CTA tile), 128 threads: 4 warps of 64x64.
// 3-stage cp.async, 2 CTAs/SM, 256-reg budget (no spills).
// ---------------------------------------------------------------------------
#define PADH 72
#define TILE_H (128 * PADH)
#define NSTAGE 3
#define GEMM_SMEM_BYTES (NSTAGE * 2 * TILE_H * 2)   // 110592

template <typename OutT>
__global__ __launch_bounds__(128, 2) void gemm_tc(
    const __half* __restrict__ A, const __half* __restrict__ Bt,
    OutT* __restrict__ C, int ldc)
{
    extern __shared__ __half smh[];
    const uint32_t sb = smem_u32(smh);

    const int tid  = threadIdx.x;
    const int wid  = tid >> 5;       // 0..3
    const int lane = tid & 31;
    const int wm = wid & 1;          // m 64-group
    const int wn = wid >> 1;         // n 64-group
    const int m0 = blockIdx.y * 128;
    const int n0 = blockIdx.x * 128;

    const __half* ga = A  + (size_t)m0 * DIM;
    const __half* gb = Bt + (size_t)n0 * DIM;

    const int lr = tid >> 3;         // 0..15
    const int lc = tid & 7;

    float acc[4][8][4];
    #pragma unroll
    for (int i = 0; i < 4; i++)
        #pragma unroll
        for (int j = 0; j < 8; j++)
            #pragma unroll
            for (int q = 0; q < 4; q++) acc[i][j][q] = 0.f;

    const uint32_t a_off = (uint32_t)(wm * 64 + (lane & 15)) * PADH + (lane >> 4) * 8;
    const uint32_t b_off = (uint32_t)(wn * 64 + ((lane >> 4) << 3) + (lane & 7)) * PADH
                         + ((lane >> 3) & 1) * 8;

    auto load_tile = [&](int chunk, int stage) {
        const uint32_t abase = sb + (uint32_t)stage * 2 * TILE_H * 2;
        const uint32_t bbase = abase + TILE_H * 2;
        const int k0 = chunk * 64;
        #pragma unroll
        for (int i = 0; i < 8; i++) {
            const int r = lr + i * 16;
            cp_async16(abase + (r * PADH + lc * 8) * 2, ga + (size_t)r * DIM + k0 + lc * 8);
        }
        #pragma unroll
        for (int i = 0; i < 8; i++) {
            const int r = lr + i * 16;
            cp_async16(bbase + (r * PADH + lc * 8) * 2, gb + (size_t)r * DIM + k0 + lc * 8);
        }
        cp_commit();
    };

    const int NCHUNK = DIM / 64;   // 16
    load_tile(0, 0);
    load_tile(1, 1);

    for (int c = 0; c < NCHUNK; c++) {
        const int stage = c % NSTAGE;
        if (c + 2 < NCHUNK) { load_tile(c + 2, (c + 2) % NSTAGE); cp_wait<1>(); }
        else                { cp_wait<0>(); }
        __syncthreads();

        const uint32_t sA = sb + (uint32_t)stage * 2 * TILE_H * 2;
        const uint32_t sB = sA + TILE_H * 2;

        #pragma unroll
        for (int kk = 0; kk < 4; kk++) {
            uint32_t af[4][4], bf[8][2];
            #pragma unroll
            for (int mt = 0; mt < 4; mt++)
                ldm_x4(af[mt], sA + (a_off + (uint32_t)(mt * 16) * PADH + kk * 16) * 2);
            #pragma unroll
            for (int p = 0; p < 4; p++) {
                uint32_t r4[4];
                ldm_x4(r4, sB + (b_off + (uint32_t)(p * 16) * PADH + kk * 16) * 2);
                bf[2 * p][0]     = r4[0];
                bf[2 * p][1]     = r4[1];
                bf[2 * p + 1][0] = r4[2];
                bf[2 * p + 1][1] = r4[3];
            }
            #pragma unroll
            for (int mt = 0; mt < 4; mt++)
                #pragma unroll
                for (int nt = 0; nt < 8; nt++)
                    mma_f16(acc[mt][nt], af[mt], bf[nt]);
        }
        __syncthreads();
    }

    #pragma unroll
    for (int mt = 0; mt < 4; mt++) {
        const int row = m0 + wm * 64 + mt * 16 + (lane >> 2);
        #pragma unroll
        for (int nt = 0; nt < 8; nt++) {
            const int col = n0 + wn * 64 + nt * 8 + (lane & 3) * 2;
            store_pair(C + (size_t)row * ldc + col, acc[mt][nt][0], acc[mt][nt][1]);
            store_pair(C + (size_t)(row + 8) * ldc + col, acc[mt][nt][2], acc[mt][nt][3]);
        }
    }
}

// ---------------------------------------------------------------------------
// Small-tile fp16 GEMM (64x64 CTA tile) for 512-row GEMMs (unchanged)
// ---------------------------------------------------------------------------
#define TILE_HS (64 * PADH)
#define GEMM_S_SMEM_BYTES (NSTAGE * 2 * TILE_HS * 2)   // 55296

template <typename OutT>
__global__ __launch_bounds__(256, 2) void gemm_tc_s(
    const __half* __restrict__ A, const __half* __restrict__ Bt,
    OutT* __restrict__ C, int ldc)
{
    extern __shared__ __half smh[];
    const uint32_t sb = smem_u32(smh);

    const int tid  = threadIdx.x;
    const int wid  = tid >> 5;
    const int lane = tid & 31;
    const int wm = wid & 3;
    const int wn = wid >> 2;
    const int m0 = blockIdx.y * 64;
    const int n0 = blockIdx.x * 64;

    const __half* ga = A  + (size_t)m0 * DIM;
    const __half* gb = Bt + (size_t)n0 * DIM;

    const int lr = tid >> 3;
    const int lc = tid & 7;

    float acc[4][4];
    #pragma unroll
    for (int j = 0; j < 4; j++)
        #pragma unroll
        for (int q = 0; q < 4; q++) acc[j][q] = 0.f;

    const uint32_t a_off = (uint32_t)(wm * 16 + (lane & 15)) * PADH + (lane >> 4) * 8;
    const uint32_t b_off = (uint32_t)(wn * 32 + ((lane >> 4) << 3) + (lane & 7)) * PADH
                         + ((lane >> 3) & 1) * 8;

    auto load_tile = [&](int chunk, int stage) {
        const uint32_t abase = sb + (uint32_t)stage * 2 * TILE_HS * 2;
        const uint32_t bbase = abase + TILE_HS * 2;
        const int k0 = chunk * 64;
        #pragma unroll
        for (int i = 0; i < 2; i++) {
            const int r = lr + i * 32;
            cp_async16(abase + (r * PADH + lc * 8) * 2, ga + (size_t)r * DIM + k0 + lc * 8);
        }
        #pragma unroll
        for (int i = 0; i < 2; i++) {
            const int r = lr + i * 32;
            cp_async16(bbase + (r * PADH + lc * 8) * 2, gb + (size_t)r * DIM + k0 + lc * 8);
        }
        cp_commit();
    };

    const int NCHUNK = DIM / 64;
    load_tile(0, 0);
    load_tile(1, 1);

    for (int c = 0; c < NCHUNK; c++) {
        const int stage = c % NSTAGE;
        if (c + 2 < NCHUNK) { load_tile(c + 2, (c + 2) % NSTAGE); cp_wait<1>(); }
        else                { cp_wait<0>(); }
        __syncthreads();

        const uint32_t sA = sb + (uint32_t)stage * 2 * TILE_HS * 2;
        const uint32_t sB = sA + TILE_HS * 2;

        #pragma unroll
        for (int kk = 0; kk < 4; kk++) {
            uint32_t af[4], bf[4][2];
            ldm_x4(af, sA + (a_off + kk * 16) * 2);
            #pragma unroll
            for (int p = 0; p < 2; p++) {
                uint32_t r4[4];
                ldm_x4(r4, sB + (b_off + (uint32_t)(p * 16) * PADH + kk * 16) * 2);
                bf[2 * p][0]     = r4[0];
                bf[2 * p][1]     = r4[1];
                bf[2 * p + 1][0] = r4[2];
                bf[2 * p + 1][1] = r4[3];
            }
            #pragma unroll
            for (int nt = 0; nt < 4; nt++)
                mma_f16(acc[nt], af, bf[nt]);
        }
        __syncthreads();
    }

    const int row = m0 + wm * 16 + (lane >> 2);
    #pragma unroll
    for (int nt = 0; nt < 4; nt++) {
        const int col = n0 + wn * 32 + nt * 8 + (lane & 3) * 2;
        store_pair(C + (size_t)row * ldc + col, acc[nt][0], acc[nt][1]);
        store_pair(C + (size_t)(row + 8) * ldc + col, acc[nt][2], acc[nt][3]);
    }
}

// ---------------------------------------------------------------------------
// Split-K flash attention on fp16 mma.sync (unchanged, known good)
// ---------------------------------------------------------------------------
#define APAD 72

__global__ __launch_bounds__(128) void attn_partial(const float* __restrict__ mask)
{
    __shared__ __half qs [64 * APAD];
    __shared__ __half ks [64 * APAD];
    __shared__ __half vsk[64 * APAD];
    __shared__ float bias[64];

    const int h = blockIdx.x;
    const int b = blockIdx.y;
    const int sp = blockIdx.z;
    const int bh = b * HEADS + h;
    const int tid = threadIdx.x;
    const int wid = tid >> 5;
    const int lane = tid & 31;
    const uint32_t sq = smem_u32(qs);
    const uint32_t sk = smem_u32(ks);
    const uint32_t sv = smem_u32(vsk);

    {
        const int q = tid >> 1;
        const int d0 = (tid & 1) * 32;
        const uint4* src = reinterpret_cast<const uint4*>(
            g_qh + (size_t)(b * N2 + q) * DIM + h * DH + d0);
        const __half2 s2 = __half2half2(__float2half(0.125f));
        #pragma unroll
        for (int i = 0; i < 4; i++) {
            uint4 u = src[i];
            __half2* hp = reinterpret_cast<__half2*>(&u);
            #pragma unroll
            for (int j = 0; j < 4; j++) hp[j] = __hmul2(hp[j], s2);
            *reinterpret_cast<uint4*>(qs + q * APAD + d0 + i * 8) = u;
        }
    }

    float o[8][4];
    #pragma unroll
    for (int j = 0; j < 8; j++)
        #pragma unroll
        for (int q = 0; q < 4; q++) o[j][q] = 0.f;
    float m0r = -1e30f, m1r = -1e30f, l0r = 0.f, l1r = 0.f;

    const uint32_t a_off = (uint32_t)(wid * 16 + (lane & 15)) * APAD + (lane >> 4) * 8;
    const uint32_t b_off = (uint32_t)(((lane >> 4) << 3) + (lane & 7)) * APAD
                         + ((lane >> 3) & 1) * 8;
    const uint32_t t_off = (uint32_t)(((lane >> 3) & 1) * 8 + (lane & 7)) * APAD
                         + (lane >> 4) * 8;
    const int tg = lane & 3;

    for (int cc = 0; cc < CH_PER_SPLIT; cc++) {
        const int key0 = (sp * CH_PER_SPLIT + cc) * 64;
        __syncthreads();

        {
            const int row = tid >> 1;
            const int cb = (tid & 1) * 4;
            const __half* ksrc = g_kvh + ((size_t)(b * NKEYS) + key0 + row) * (2 * DIM) + h * DH;
            const __half* vsrc = ksrc + DIM;
            #pragma unroll
            for (int i = 0; i < 4; i++)
                cp_async16(sk + (row * APAD + (cb + i) * 8) * 2, ksrc + (cb + i) * 8);
            #pragma unroll
            for (int i = 0; i < 4; i++)
                cp_async16(sv + (row * APAD + (cb + i) * 8) * 2, vsrc + (cb + i) * 8);
            cp_commit();
        }
        if (tid < 64) {
            const int kg = key0 + tid;
            bias[tid] = (kg < N1) ? (mask[(size_t)b * N1 + kg] - 1.0f) * 100.0f : 0.f;
        }
        cp_wait<0>();
        __syncthreads();

        float s[8][4];
        #pragma unroll
        for (int j = 0; j < 8; j++)
            #pragma unroll
            for (int q = 0; q < 4; q++) s[j][q] = 0.f;
        #pragma unroll
        for (int kk = 0; kk < 4; kk++) {
            uint32_t af[4], bf[8][2];
            ldm_x4(af, sq + (a_off + kk * 16) * 2);
            #pragma unroll
            for (int p = 0; p < 4; p++) {
                uint32_t r4[4];
                ldm_x4(r4, sk + (b_off + (uint32_t)(p * 16) * APAD + kk * 16) * 2);
                bf[2 * p][0]     = r4[0];
                bf[2 * p][1]     = r4[1];
                bf[2 * p + 1][0] = r4[2];
                bf[2 * p + 1][1] = r4[3];
            }
            #pragma unroll
            for (int nt = 0; nt < 8; nt++)
                mma_f16(s[nt], af, bf[nt]);
        }

        float c0 = -1e30f, c1 = -1e30f;
        #pragma unroll
        for (int nt = 0; nt < 8; nt++) {
            const float b0 = bias[nt * 8 + 2 * tg];
            const float b1 = bias[nt * 8 + 2 * tg + 1];
            s[nt][0] += b0; s[nt][1] += b1; s[nt][2] += b0; s[nt][3] += b1;
            c0 = fmaxf(c0, fmaxf(s[nt][0], s[nt][1]));
            c1 = fmaxf(c1, fmaxf(s[nt][2], s[nt][3]));
        }
        c0 = fmaxf(c0, __shfl_xor_sync(0xffffffffu, c0, 1));
        c0 = fmaxf(c0, __shfl_xor_sync(0xffffffffu, c0, 2));
        c1 = fmaxf(c1, __shfl_xor_sync(0xffffffffu, c1, 1));
        c1 = fmaxf(c1, __shfl_xor_sync(0xffffffffu, c1, 2));

        const float mn0 = fmaxf(m0r, c0);
        const float mn1 = fmaxf(m1r, c1);
        const float al0 = __expf(m0r - mn0);
        const float al1 = __expf(m1r - mn1);
        float cs0 = 0.f, cs1 = 0.f;
        #pragma unroll
        for (int nt = 0; nt < 8; nt++) {
            s[nt][0] = __expf(s[nt][0] - mn0); cs0 += s[nt][0];
            s[nt][1] = __expf(s[nt][1] - mn0); cs0 += s[nt][1];
            s[nt][2] = __expf(s[nt][2] - mn1); cs1 += s[nt][2];
            s[nt][3] = __expf(s[nt][3] - mn1); cs1 += s[nt][3];
        }
        cs0 += __shfl_xor_sync(0xffffffffu, cs0, 1);
        cs0 += __shfl_xor_sync(0xffffffffu, cs0, 2);
        cs1 += __shfl_xor_sync(0xffffffffu, cs1, 1);
        cs1 += __shfl_xor_sync(0xffffffffu, cs1, 2);
        l0r = l0r * al0 + cs0; m0r = mn0;
        l1r = l1r * al1 + cs1; m1r = mn1;
        #pragma unroll
        for (int nt = 0; nt < 8; nt++) {
            o[nt][0] *= al0; o[nt][1] *= al0;
            o[nt][2] *= al1; o[nt][3] *= al1;
        }

        #pragma unroll
        for (int kv = 0; kv < 4; kv++) {
            uint32_t pa[4];
            pa[0] = pack_h2(s[2 * kv][0],     s[2 * kv][1]);
            pa[1] = pack_h2(s[2 * kv][2],     s[2 * kv][3]);
            pa[2] = pack_h2(s[2 * kv + 1][0], s[2 * kv + 1][1]);
            pa[3] = pack_h2(s[2 * kv + 1][2], s[2 * kv + 1][3]);
            uint32_t bf[8][2];
            #pragma unroll
            for (int p = 0; p < 4; p++) {
                uint32_t r4[4];
                ldm_x4_t(r4, sv + (t_off + (uint32_t)(kv * 16) * APAD + p * 16) * 2);
                bf[2 * p][0]     = r4[0];
                bf[2 * p][1]     = r4[1];
                bf[2 * p + 1][0] = r4[2];
                bf[2 * p + 1][1] = r4[3];
            }
            #pragma unroll
            for (int nt = 0; nt < 8; nt++)
                mma_f16(o[nt], pa, bf[nt]);
        }
    }

    const int g = lane >> 2;
    const int row0 = wid * 16 + g;
    float* po = g_pO + ((size_t)(bh * NSPLIT + sp) * N2) * DH;
    #pragma unroll
    for (int nt = 0; nt < 8; nt++) {
        *reinterpret_cast<float2*>(po + (size_t)row0 * DH + nt * 8 + 2 * tg) =
            make_float2(o[nt][0], o[nt][1]);
        *reinterpret_cast<float2*>(po + (size_t)(row0 + 8) * DH + nt * 8 + 2 * tg) =
            make_float2(o[nt][2], o[nt][3]);
    }
    if (tg == 0) {
        float* pml = g_pml + (size_t)(bh * NSPLIT + sp) * 2 * N2;
        pml[row0]          = m0r;
        pml[row0 + 8]      = m1r;
        pml[N2 + row0]     = l0r;
        pml[N2 + row0 + 8] = l1r;
    }
}

// ---------------------------------------------------------------------------
// Merge partials -> g_attnh (half)
// ---------------------------------------------------------------------------
__global__ __launch_bounds__(256) void attn_merge()
{
    const int bh = blockIdx.x;
    const int b = bh / HEADS;
    const int h = bh - b * HEADS;
    const int tid = threadIdx.x;
    const int q  = tid >> 2;
    const int dq = tid & 3;

    float ms[NSPLIT], ls[NSPLIT];
    float M = -1e30f;
    #pragma unroll
    for (int s = 0; s < NSPLIT; s++) {
        const float* pml = g_pml + (size_t)(bh * NSPLIT + s) * 2 * N2;
        ms[s] = pml[q];
        ls[s] = pml[N2 + q];
        M = fmaxf(M, ms[s]);
    }
    float w[NSPLIT], lt = 0.f;
    #pragma unroll
    for (int s = 0; s < NSPLIT; s++) {
        w[s] = __expf(ms[s] - M);
        lt += ls[s] * w[s];
    }
    const float inv = 1.0f / lt;

    __half* dst = g_attnh + ((size_t)(b * N2 + q)) * DIM + h * DH + dq * 16;
    #pragma unroll
    for (int j = 0; j < 4; j++) {
        float4 acc = make_float4(0.f, 0.f, 0.f, 0.f);
        #pragma unroll
        for (int s = 0; s < NSPLIT; s++) {
            const float4 v = *reinterpret_cast<const float4*>(
                g_pO + ((size_t)(bh * NSPLIT + s) * N2 + q) * DH + dq * 16 + j * 4);
            acc.x += w[s] * v.x;
            acc.y += w[s] * v.y;
            acc.z += w[s] * v.z;
            acc.w += w[s] * v.w;
        }
        __half2 h0 = make_half2(__float2half_rn(acc.x * inv), __float2half_rn(acc.y * inv));
        __half2 h1 = make_half2(__float2half_rn(acc.z * inv), __float2half_rn(acc.w * inv));
        *reinterpret_cast<__half2*>(dst + j * 4)     = h0;
        *reinterpret_cast<__half2*>(dst + j * 4 + 2) = h1;
    }
}

// ---------------------------------------------------------------------------
// Launch (single stream, serial)
// ---------------------------------------------------------------------------
extern "C" void kernel_launch(void* const* d_in, const int* in_sizes, int n_in,
                              void* d_out, int out_size)
{
    const float* x       = (const float*)d_in[0];
    const float* latents = (const float*)d_in[1];
    const float* mask    = (const float*)d_in[2];
    const float* ln1g    = (const float*)d_in[3];
    const float* ln1b    = (const float*)d_in[4];
    const float* ln2g    = (const float*)d_in[5];
    const float* ln2b    = (const float*)d_in[6];
    const float* Wq      = (const float*)d_in[7];
    const float* Wkv     = (const float*)d_in[8];
    const float* Wout    = (const float*)d_in[9];
    float* out = (float*)d_out;

    __half *p_kvin, *p_lnh, *p_qh, *p_kvh, *p_attnh, *p_wkvT, *p_wqT, *p_woT;
    cudaGetSymbolAddress((void**)&p_kvin,  g_kvin);
    cudaGetSymbolAddress((void**)&p_lnh,   g_lnh);
    cudaGetSymbolAddress((void**)&p_qh,    g_qh);
    cudaGetSymbolAddress((void**)&p_kvh,   g_kvh);
    cudaGetSymbolAddress((void**)&p_attnh, g_attnh);
    cudaGetSymbolAddress((void**)&p_wkvT,  g_wkvT);
    cudaGetSymbolAddress((void**)&p_wqT,   g_wqT);
    cudaGetSymbolAddress((void**)&p_woT,   g_woT);

    static bool attr_set = false;
    if (!attr_set) {
        cudaFuncSetAttribute(gemm_tc<__half>, cudaFuncAttributeMaxDynamicSharedMemorySize,
                             GEMM_SMEM_BYTES);
        cudaFuncSetAttribute(gemm_tc_s<__half>, cudaFuncAttributeMaxDynamicSharedMemorySize,
                             GEMM_S_SMEM_BYTES);
        cudaFuncSetAttribute(gemm_tc_s<float>, cudaFuncAttributeMaxDynamicSharedMemorySize,
                             GEMM_S_SMEM_BYTES);
        attr_set = true;
    }

    // 0) Transpose + fp16-round weights
    transpose2_kernel<<<dim3(DIM / 32, DIM / 32, 2), dim3(32, 8)>>>(Wq, Wout, p_wqT, p_woT);
    transpose_kernel<<<dim3(2 * DIM / 32, DIM / 32), dim3(32, 8)>>>(Wkv, p_wkvT, 2 * DIM);

    // 1) LayerNorms (half outputs; 4 rows per block)
    ln_kernel<<<MROWS / 4, 256>>>(x, latents, ln1g, ln1b, ln2g, ln2b);

    // 2) KV GEMM (fp16 mma, half output) — 128 threads, 64x64 warp tiles
    gemm_tc<__half><<<dim3(2 * DIM / 128, MROWS / 128), 128, GEMM_SMEM_BYTES>>>(
        p_kvin, p_wkvT, p_kvh, 2 * DIM);

    // 3) Q GEMM (small tiles, half output)
    gemm_tc_s<__half><<<dim3(DIM / 64, BATCH * N2 / 64), 256, GEMM_S_SMEM_BYTES>>>(
        p_lnh, p_wqT, p_qh, DIM);

    // 4) Attention: fp16-MMA split-K partials + merge
    attn_partial<<<dim3(HEADS, BATCH, NSPLIT), 128>>>(mask);
    attn_merge<<<BATCH * HEADS, 256>>>();

    // 5) Out GEMM (small tiles, float output) -> d_out
    gemm_tc_s<float><<<dim3(DIM / 64, BATCH * N2 / 64), 256, GEMM_S_SMEM_BYTES>>>(
        p_attnh, p_woT, out, DIM);
}

// round 15
// speedup vs baseline: 1.5896x; 1.0350x over previous
#include <cuda_runtime.h>
#include <cuda_fp16.h>
#include <cstdint>

// ---------------------------------------------------------------------------
// PerceiverAttention, sm_103 — Round 14:
//   * GEMM mainloops: ONE __syncthreads per chunk (prefetch moved after the
//     barrier; trailing barrier removed — provably safe with 3 stages)
//   * Q GEMM fused into the KV GEMM launch (rides the 95%-idle tail wave)
// ---------------------------------------------------------------------------

#define BATCH 8
#define N1 4096
#define N2 64
#define NKEYS 4160
#define DIM 1024
#define HEADS 16
#define DH 64
#define MROWS (BATCH * NKEYS)   // 33280
#define NSPLIT 5
#define CH_PER_SPLIT 13
#define KV_YTILES (MROWS / 128) // 260

__device__ __half g_kvin[(size_t)MROWS * DIM];
__device__ __half g_lnh [(size_t)BATCH * N2 * DIM];
__device__ __half g_qh  [(size_t)BATCH * N2 * DIM];
__device__ __half g_kvh [(size_t)MROWS * 2 * DIM];
__device__ __half g_attnh[(size_t)BATCH * N2 * DIM];
__device__ __half g_wkvT[(size_t)2 * DIM * DIM];
__device__ __half g_wqT [(size_t)DIM * DIM];
__device__ __half g_woT [(size_t)DIM * DIM];
__device__ float  g_pO  [(size_t)BATCH * HEADS * NSPLIT * N2 * DH];
__device__ float  g_pml [(size_t)BATCH * HEADS * NSPLIT * 2 * N2];

// ---------------------------------------------------------------------------
// Helpers
// ---------------------------------------------------------------------------
__device__ __forceinline__ uint32_t smem_u32(const void* p) {
    uint32_t a;
    asm("{ .reg .u64 t; cvta.to.shared.u64 t, %1; cvt.u32.u64 %0, t; }" : "=r"(a) : "l"(p));
    return a;
}
__device__ __forceinline__ void cp_async16(uint32_t dst, const void* src) {
    asm volatile("cp.async.cg.shared.global [%0], [%1], 16;" :: "r"(dst), "l"(src));
}
__device__ __forceinline__ void cp_commit() {
    asm volatile("cp.async.commit_group;" ::: "memory");
}
template <int N>
__device__ __forceinline__ void cp_wait() {
    asm volatile("cp.async.wait_group %0;" :: "n"(N) : "memory");
}
__device__ __forceinline__ void mma_f16(float* d, const uint32_t* a, const uint32_t* b) {
    asm volatile(
        "mma.sync.aligned.m16n8k16.row.col.f32.f16.f16.f32 "
        "{%0,%1,%2,%3}, {%4,%5,%6,%7}, {%8,%9}, {%0,%1,%2,%3};"
        : "+f"(d[0]), "+f"(d[1]), "+f"(d[2]), "+f"(d[3])
        : "r"(a[0]), "r"(a[1]), "r"(a[2]), "r"(a[3]), "r"(b[0]), "r"(b[1]));
}
__device__ __forceinline__ void ldm_x4(uint32_t* r, uint32_t addr) {
    asm volatile("ldmatrix.sync.aligned.m8n8.x4.shared.b16 {%0,%1,%2,%3}, [%4];"
        : "=r"(r[0]), "=r"(r[1]), "=r"(r[2]), "=r"(r[3]) : "r"(addr));
}
__device__ __forceinline__ void ldm_x4_t(uint32_t* r, uint32_t addr) {
    asm volatile("ldmatrix.sync.aligned.m8n8.x4.trans.shared.b16 {%0,%1,%2,%3}, [%4];"
        : "=r"(r[0]), "=r"(r[1]), "=r"(r[2]), "=r"(r[3]) : "r"(addr));
}
__device__ __forceinline__ uint32_t pack_h2(float a, float b) {
    __half2 h = __floats2half2_rn(a, b);
    return *reinterpret_cast<uint32_t*>(&h);
}
__device__ __forceinline__ void store_pair(float* p, float a, float b) {
    *reinterpret_cast<float2*>(p) = make_float2(a, b);
}
__device__ __forceinline__ void store_pair(__half* p, float a, float b) {
    *reinterpret_cast<__half2*>(p) = make_half2(__float2half_rn(a), __float2half_rn(b));
}

// ---------------------------------------------------------------------------
// Weight transposes
// ---------------------------------------------------------------------------
__global__ __launch_bounds__(256) void transpose_kernel(
    const float* __restrict__ in, __half* __restrict__ out, int ncols)
{
    __shared__ float t[32][33];
    const int bx = blockIdx.x * 32;
    const int by = blockIdx.y * 32;
    const int x = threadIdx.x;
    const int y = threadIdx.y;
    #pragma unroll
    for (int i = 0; i < 32; i += 8)
        t[y + i][x] = in[(size_t)(by + y + i) * ncols + bx + x];
    __syncthreads();
    #pragma unroll
    for (int i = 0; i < 32; i += 8)
        out[(size_t)(bx + y + i) * DIM + by + x] = __float2half_rn(t[x][y + i]);
}

__global__ __launch_bounds__(256) void transpose2_kernel(
    const float* __restrict__ inq, const float* __restrict__ ino,
    __half* __restrict__ outq, __half* __restrict__ outo)
{
    __shared__ float t[32][33];
    const float* in  = blockIdx.z ? ino  : inq;
    __half*      out = blockIdx.z ? outo : outq;
    const int bx = blockIdx.x * 32;
    const int by = blockIdx.y * 32;
    const int x = threadIdx.x;
    const int y = threadIdx.y;
    #pragma unroll
    for (int i = 0; i < 32; i += 8)
        t[y + i][x] = in[(size_t)(by + y + i) * DIM + bx + x];
    __syncthreads();
    #pragma unroll
    for (int i = 0; i < 32; i += 8)
        out[(size_t)(bx + y + i) * DIM + by + x] = __float2half_rn(t[x][y + i]);
}

// ---------------------------------------------------------------------------
// LayerNorm -> half outputs. 4 rows/block, 64 threads/row (MLP=4).
// ---------------------------------------------------------------------------
__global__ __launch_bounds__(256) void ln_kernel(
    const float* __restrict__ x, const float* __restrict__ lat,
    const float* __restrict__ g1, const float* __restrict__ b1,
    const float* __restrict__ g2, const float* __restrict__ b2)
{
    __shared__ float red[16];
    const int rid  = threadIdx.x >> 6;
    const int tl   = threadIdx.x & 63;
    const int wid  = threadIdx.x >> 5;
    const int lane = threadIdx.x & 31;

    const int r  = blockIdx.x * 4 + rid;
    const int bb = r / NKEYS;
    const int i  = r - bb * NKEYS;

    const float* src;
    const float* g;
    const float* be;
    __half* dst2 = nullptr;
    if (i < N1) {
        src = x + ((size_t)bb * N1 + i) * DIM;
        g = g1; be = b1;
    } else {
        const int j = i - N1;
        src = lat + ((size_t)bb * N2 + j) * DIM;
        g = g2; be = b2;
        dst2 = g_lnh + ((size_t)bb * N2 + j) * DIM;
    }
    __half* dst = g_kvin + (size_t)r * DIM;

    const float4* s4 = reinterpret_cast<const float4*>(src);
    float4 v[4];
    #pragma unroll
    for (int p = 0; p < 4; p++) v[p] = s4[tl + 64 * p];

    float s = 0.f, sq = 0.f;
    #pragma unroll
    for (int p = 0; p < 4; p++) {
        s  += v[p].x + v[p].y + v[p].z + v[p].w;
        sq += v[p].x*v[p].x + v[p].y*v[p].y + v[p].z*v[p].z + v[p].w*v[p].w;
    }
    #pragma unroll
    for (int o = 16; o > 0; o >>= 1) {
        s  += __shfl_xor_sync(0xffffffffu, s, o);
        sq += __shfl_xor_sync(0xffffffffu, sq, o);
    }
    if (lane == 0) { red[wid * 2] = s; red[wid * 2 + 1] = sq; }
    __syncthreads();
    const float S  = red[rid * 4]     + red[rid * 4 + 2];
    const float SQ = red[rid * 4 + 1] + red[rid * 4 + 3];

    const float mu   = S * (1.0f / DIM);
    const float var  = SQ * (1.0f / DIM) - mu * mu;
    const float rstd = rsqrtf(var + 1e-5f);

    const float4* g4 = reinterpret_cast<const float4*>(g);
    const float4* b4 = reinterpret_cast<const float4*>(be);
    #pragma unroll
    for (int p = 0; p < 4; p++) {
        const float4 gv = g4[tl + 64 * p];
        const float4 bv = b4[tl + 64 * p];
        uint2 u;
        __half2* hp = reinterpret_cast<__half2*>(&u);
        hp[0] = make_half2(__float2half_rn((v[p].x - mu) * rstd * gv.x + bv.x),
                           __float2half_rn((v[p].y - mu) * rstd * gv.y + bv.y));
        hp[1] = make_half2(__float2half_rn((v[p].z - mu) * rstd * gv.z + bv.z),
                           __float2half_rn((v[p].w - mu) * rstd * gv.w + bv.w));
        reinterpret_cast<uint2*>(dst)[tl + 64 * p] = u;
        if (dst2) reinterpret_cast<uint2*>(dst2)[tl + 64 * p] = u;
    }
}

// ---------------------------------------------------------------------------
// Fused KV+Q GEMM: 128x128 CTA tile, 128 threads (4 warps of 64x64),
// 3-stage cp.async, ONE barrier per chunk, 2 CTAs/SM.
// blockIdx.y <  260 : g_kvin @ g_wkvT -> g_kvh  (ldc 2048)
// blockIdx.y >= 260 : g_lnh  @ g_wqT  -> g_qh   (ldc 1024, bx<8 only)
// ---------------------------------------------------------------------------
#define PADH 72
#define TILE_H (128 * PADH)
#define NSTAGE 3
#define GEMM_SMEM_BYTES (NSTAGE * 2 * TILE_H * 2)   // 110592

__global__ __launch_bounds__(128, 2) void gemm_fused(void)
{
    extern __shared__ __half smh[];
    const uint32_t sb = smem_u32(smh);

    const int by = blockIdx.y;
    const int bx = blockIdx.x;
    const __half* A;
    const __half* Bt;
    __half* C;
    int ldc, m0;
    if (by < KV_YTILES) {
        A = g_kvin; Bt = g_wkvT; C = g_kvh; ldc = 2 * DIM; m0 = by * 128;
    } else {
        if (bx >= DIM / 128) return;
        A = g_lnh;  Bt = g_wqT;  C = g_qh;  ldc = DIM;     m0 = (by - KV_YTILES) * 128;
    }
    const int n0 = bx * 128;

    const int tid  = threadIdx.x;
    const int wid  = tid >> 5;
    const int lane = tid & 31;
    const int wm = wid & 1;
    const int wn = wid >> 1;

    const __half* ga = A  + (size_t)m0 * DIM;
    const __half* gb = Bt + (size_t)n0 * DIM;

    const int lr = tid >> 3;         // 0..15
    const int lc = tid & 7;

    float acc[4][8][4];
    #pragma unroll
    for (int i = 0; i < 4; i++)
        #pragma unroll
        for (int j = 0; j < 8; j++)
            #pragma unroll
            for (int q = 0; q < 4; q++) acc[i][j][q] = 0.f;

    const uint32_t a_off = (uint32_t)(wm * 64 + (lane & 15)) * PADH + (lane >> 4) * 8;
    const uint32_t b_off = (uint32_t)(wn * 64 + ((lane >> 4) << 3) + (lane & 7)) * PADH
                         + ((lane >> 3) & 1) * 8;

    auto load_tile = [&](int chunk, int stage) {
        const uint32_t abase = sb + (uint32_t)stage * 2 * TILE_H * 2;
        const uint32_t bbase = abase + TILE_H * 2;
        const int k0 = chunk * 64;
        #pragma unroll
        for (int i = 0; i < 8; i++) {
            const int r = lr + i * 16;
            cp_async16(abase + (r * PADH + lc * 8) * 2, ga + (size_t)r * DIM + k0 + lc * 8);
        }
        #pragma unroll
        for (int i = 0; i < 8; i++) {
            const int r = lr + i * 16;
            cp_async16(bbase + (r * PADH + lc * 8) * 2, gb + (size_t)r * DIM + k0 + lc * 8);
        }
        cp_commit();
    };

    const int NCHUNK = DIM / 64;   // 16
    load_tile(0, 0);
    load_tile(1, 1);

    for (int c = 0; c < NCHUNK; c++) {
        const int stage = c % NSTAGE;
        if (c == NCHUNK - 1) cp_wait<0>();
        else                 cp_wait<1>();
        __syncthreads();
        if (c + 2 < NCHUNK) load_tile(c + 2, (c + 2) % NSTAGE);

        const uint32_t sA = sb + (uint32_t)stage * 2 * TILE_H * 2;
        const uint32_t sB = sA + TILE_H * 2;

        #pragma unroll
        for (int kk = 0; kk < 4; kk++) {
            uint32_t af[4][4], bf[8][2];
            #pragma unroll
            for (int mt = 0; mt < 4; mt++)
                ldm_x4(af[mt], sA + (a_off + (uint32_t)(mt * 16) * PADH + kk * 16) * 2);
            #pragma unroll
            for (int p = 0; p < 4; p++) {
                uint32_t r4[4];
                ldm_x4(r4, sB + (b_off + (uint32_t)(p * 16) * PADH + kk * 16) * 2);
                bf[2 * p][0]     = r4[0];
                bf[2 * p][1]     = r4[1];
                bf[2 * p + 1][0] = r4[2];
                bf[2 * p + 1][1] = r4[3];
            }
            #pragma unroll
            for (int mt = 0; mt < 4; mt++)
                #pragma unroll
                for (int nt = 0; nt < 8; nt++)
                    mma_f16(acc[mt][nt], af[mt], bf[nt]);
        }
    }

    #pragma unroll
    for (int mt = 0; mt < 4; mt++) {
        const int row = m0 + wm * 64 + mt * 16 + (lane >> 2);
        #pragma unroll
        for (int nt = 0; nt < 8; nt++) {
            const int col = n0 + wn * 64 + nt * 8 + (lane & 3) * 2;
            store_pair(C + (size_t)row * ldc + col, acc[mt][nt][0], acc[mt][nt][1]);
            store_pair(C + (size_t)(row + 8) * ldc + col, acc[mt][nt][2], acc[mt][nt][3]);
        }
    }
}

// ---------------------------------------------------------------------------
// Small-tile fp16 GEMM (64x64 CTA tile) — Out GEMM. One barrier per chunk.
// ---------------------------------------------------------------------------
#define TILE_HS (64 * PADH)
#define GEMM_S_SMEM_BYTES (NSTAGE * 2 * TILE_HS * 2)   // 55296

template <typename OutT>
__global__ __launch_bounds__(256, 2) void gemm_tc_s(
    const __half* __restrict__ A, const __half* __restrict__ Bt,
    OutT* __restrict__ C, int ldc)
{
    extern __shared__ __half smh[];
    const uint32_t sb = smem_u32(smh);

    const int tid  = threadIdx.x;
    const int wid  = tid >> 5;
    const int lane = tid & 31;
    const int wm = wid & 3;
    const int wn = wid >> 2;
    const int m0 = blockIdx.y * 64;
    const int n0 = blockIdx.x * 64;

    const __half* ga = A  + (size_t)m0 * DIM;
    const __half* gb = Bt + (size_t)n0 * DIM;

    const int lr = tid >> 3;
    const int lc = tid & 7;

    float acc[4][4];
    #pragma unroll
    for (int j = 0; j < 4; j++)
        #pragma unroll
        for (int q = 0; q < 4; q++) acc[j][q] = 0.f;

    const uint32_t a_off = (uint32_t)(wm * 16 + (lane & 15)) * PADH + (lane >> 4) * 8;
    const uint32_t b_off = (uint32_t)(wn * 32 + ((lane >> 4) << 3) + (lane & 7)) * PADH
                         + ((lane >> 3) & 1) * 8;

    auto load_tile = [&](int chunk, int stage) {
        const uint32_t abase = sb + (uint32_t)stage * 2 * TILE_HS * 2;
        const uint32_t bbase = abase + TILE_HS * 2;
        const int k0 = chunk * 64;
        #pragma unroll
        for (int i = 0; i < 2; i++) {
            const int r = lr + i * 32;
            cp_async16(abase + (r * PADH + lc * 8) * 2, ga + (size_t)r * DIM + k0 + lc * 8);
        }
        #pragma unroll
        for (int i = 0; i < 2; i++) {
            const int r = lr + i * 32;
            cp_async16(bbase + (r * PADH + lc * 8) * 2, gb + (size_t)r * DIM + k0 + lc * 8);
        }
        cp_commit();
    };

    const int NCHUNK = DIM / 64;
    load_tile(0, 0);
    load_tile(1, 1);

    for (int c = 0; c < NCHUNK; c++) {
        const int stage = c % NSTAGE;
        if (c == NCHUNK - 1) cp_wait<0>();
        else                 cp_wait<1>();
        __syncthreads();
        if (c + 2 < NCHUNK) load_tile(c + 2, (c + 2) % NSTAGE);

        const uint32_t sA = sb + (uint32_t)stage * 2 * TILE_HS * 2;
        const uint32_t sB = sA + TILE_HS * 2;

        #pragma unroll
        for (int kk = 0; kk < 4; kk++) {
            uint32_t af[4], bf[4][2];
            ldm_x4(af, sA + (a_off + kk * 16) * 2);
            #pragma unroll
            for (int p = 0; p < 2; p++) {
                uint32_t r4[4];
                ldm_x4(r4, sB + (b_off + (uint32_t)(p * 16) * PADH + kk * 16) * 2);
                bf[2 * p][0]     = r4[0];
                bf[2 * p][1]     = r4[1];
                bf[2 * p + 1][0] = r4[2];
                bf[2 * p + 1][1] = r4[3];
            }
            #pragma unroll
            for (int nt = 0; nt < 4; nt++)
                mma_f16(acc[nt], af, bf[nt]);
        }
    }

    const int row = m0 + wm * 16 + (lane >> 2);
    #pragma unroll
    for (int nt = 0; nt < 4; nt++) {
        const int col = n0 + wn * 32 + nt * 8 + (lane & 3) * 2;
        store_pair(C + (size_t)row * ldc + col, acc[nt][0], acc[nt][1]);
        store_pair(C + (size_t)(row + 8) * ldc + col, acc[nt][2], acc[nt][3]);
    }
}

// ---------------------------------------------------------------------------
// Split-K flash attention on fp16 mma.sync (unchanged, known good)
// ---------------------------------------------------------------------------
#define APAD 72

__global__ __launch_bounds__(128) void attn_partial(const float* __restrict__ mask)
{
    __shared__ __half qs [64 * APAD];
    __shared__ __half ks [64 * APAD];
    __shared__ __half vsk[64 * APAD];
    __shared__ float bias[64];

    const int h = blockIdx.x;
    const int b = blockIdx.y;
    const int sp = blockIdx.z;
    const int bh = b * HEADS + h;
    const int tid = threadIdx.x;
    const int wid = tid >> 5;
    const int lane = tid & 31;
    const uint32_t sq = smem_u32(qs);
    const uint32_t sk = smem_u32(ks);
    const uint32_t sv = smem_u32(vsk);

    {
        const int q = tid >> 1;
        const int d0 = (tid & 1) * 32;
        const uint4* src = reinterpret_cast<const uint4*>(
            g_qh + (size_t)(b * N2 + q) * DIM + h * DH + d0);
        const __half2 s2 = __half2half2(__float2half(0.125f));
        #pragma unroll
        for (int i = 0; i < 4; i++) {
            uint4 u = src[i];
            __half2* hp = reinterpret_cast<__half2*>(&u);
            #pragma unroll
            for (int j = 0; j < 4; j++) hp[j] = __hmul2(hp[j], s2);
            *reinterpret_cast<uint4*>(qs + q * APAD + d0 + i * 8) = u;
        }
    }

    float o[8][4];
    #pragma unroll
    for (int j = 0; j < 8; j++)
        #pragma unroll
        for (int q = 0; q < 4; q++) o[j][q] = 0.f;
    float m0r = -1e30f, m1r = -1e30f, l0r = 0.f, l1r = 0.f;

    const uint32_t a_off = (uint32_t)(wid * 16 + (lane & 15)) * APAD + (lane >> 4) * 8;
    const uint32_t b_off = (uint32_t)(((lane >> 4) << 3) + (lane & 7)) * APAD
                         + ((lane >> 3) & 1) * 8;
    const uint32_t t_off = (uint32_t)(((lane >> 3) & 1) * 8 + (lane & 7)) * APAD
                         + (lane >> 4) * 8;
    const int tg = lane & 3;

    for (int cc = 0; cc < CH_PER_SPLIT; cc++) {
        const int key0 = (sp * CH_PER_SPLIT + cc) * 64;
        __syncthreads();

        {
            const int row = tid >> 1;
            const int cb = (tid & 1) * 4;
            const __half* ksrc = g_kvh + ((size_t)(b * NKEYS) + key0 + row) * (2 * DIM) + h * DH;
            const __half* vsrc = ksrc + DIM;
            #pragma unroll
            for (int i = 0; i < 4; i++)
                cp_async16(sk + (row * APAD + (cb + i) * 8) * 2, ksrc + (cb + i) * 8);
            #pragma unroll
            for (int i = 0; i < 4; i++)
                cp_async16(sv + (row * APAD + (cb + i) * 8) * 2, vsrc + (cb + i) * 8);
            cp_commit();
        }
        if (tid < 64) {
            const int kg = key0 + tid;
            bias[tid] = (kg < N1) ? (mask[(size_t)b * N1 + kg] - 1.0f) * 100.0f : 0.f;
        }
        cp_wait<0>();
        __syncthreads();

        float s[8][4];
        #pragma unroll
        for (int j = 0; j < 8; j++)
            #pragma unroll
            for (int q = 0; q < 4; q++) s[j][q] = 0.f;
        #pragma unroll
        for (int kk = 0; kk < 4; kk++) {
            uint32_t af[4], bf[8][2];
            ldm_x4(af, sq + (a_off + kk * 16) * 2);
            #pragma unroll
            for (int p = 0; p < 4; p++) {
                uint32_t r4[4];
                ldm_x4(r4, sk + (b_off + (uint32_t)(p * 16) * APAD + kk * 16) * 2);
                bf[2 * p][0]     = r4[0];
                bf[2 * p][1]     = r4[1];
                bf[2 * p + 1][0] = r4[2];
                bf[2 * p + 1][1] = r4[3];
            }
            #pragma unroll
            for (int nt = 0; nt < 8; nt++)
                mma_f16(s[nt], af, bf[nt]);
        }

        float c0 = -1e30f, c1 = -1e30f;
        #pragma unroll
        for (int nt = 0; nt < 8; nt++) {
            const float b0 = bias[nt * 8 + 2 * tg];
            const float b1 = bias[nt * 8 + 2 * tg + 1];
            s[nt][0] += b0; s[nt][1] += b1; s[nt][2] += b0; s[nt][3] += b1;
            c0 = fmaxf(c0, fmaxf(s[nt][0], s[nt][1]));
            c1 = fmaxf(c1, fmaxf(s[nt][2], s[nt][3]));
        }
        c0 = fmaxf(c0, __shfl_xor_sync(0xffffffffu, c0, 1));
        c0 = fmaxf(c0, __shfl_xor_sync(0xffffffffu, c0, 2));
        c1 = fmaxf(c1, __shfl_xor_sync(0xffffffffu, c1, 1));
        c1 = fmaxf(c1, __shfl_xor_sync(0xffffffffu, c1, 2));

        const float mn0 = fmaxf(m0r, c0);
        const float mn1 = fmaxf(m1r, c1);
        const float al0 = __expf(m0r - mn0);
        const float al1 = __expf(m1r - mn1);
        float cs0 = 0.f, cs1 = 0.f;
        #pragma unroll
        for (int nt = 0; nt < 8; nt++) {
            s[nt][0] = __expf(s[nt][0] - mn0); cs0 += s[nt][0];
            s[nt][1] = __expf(s[nt][1] - mn0); cs0 += s[nt][1];
            s[nt][2] = __expf(s[nt][2] - mn1); cs1 += s[nt][2];
            s[nt][3] = __expf(s[nt][3] - mn1); cs1 += s[nt][3];
        }
        cs0 += __shfl_xor_sync(0xffffffffu, cs0, 1);
        cs0 += __shfl_xor_sync(0xffffffffu, cs0, 2);
        cs1 += __shfl_xor_sync(0xffffffffu, cs1, 1);
        cs1 += __shfl_xor_sync(0xffffffffu, cs1, 2);
        l0r = l0r * al0 + cs0; m0r = mn0;
        l1r = l1r * al1 + cs1; m1r = mn1;
        #pragma unroll
        for (int nt = 0; nt < 8; nt++) {
            o[nt][0] *= al0; o[nt][1] *= al0;
            o[nt][2] *= al1; o[nt][3] *= al1;
        }

        #pragma unroll
        for (int kv = 0; kv < 4; kv++) {
            uint32_t pa[4];
            pa[0] = pack_h2(s[2 * kv][0],     s[2 * kv][1]);
            pa[1] = pack_h2(s[2 * kv][2],     s[2 * kv][3]);
            pa[2] = pack_h2(s[2 * kv + 1][0], s[2 * kv + 1][1]);
            pa[3] = pack_h2(s[2 * kv + 1][2], s[2 * kv + 1][3]);
            uint32_t bf[8][2];
            #pragma unroll
            for (int p = 0; p < 4; p++) {
                uint32_t r4[4];
                ldm_x4_t(r4, sv + (t_off + (uint32_t)(kv * 16) * APAD + p * 16) * 2);
                bf[2 * p][0]     = r4[0];
                bf[2 * p][1]     = r4[1];
                bf[2 * p + 1][0] = r4[2];
                bf[2 * p + 1][1] = r4[3];
            }
            #pragma unroll
            for (int nt = 0; nt < 8; nt++)
                mma_f16(o[nt], pa, bf[nt]);
        }
    }

    const int g = lane >> 2;
    const int row0 = wid * 16 + g;
    float* po = g_pO + ((size_t)(bh * NSPLIT + sp) * N2) * DH;
    #pragma unroll
    for (int nt = 0; nt < 8; nt++) {
        *reinterpret_cast<float2*>(po + (size_t)row0 * DH + nt * 8 + 2 * tg) =
            make_float2(o[nt][0], o[nt][1]);
        *reinterpret_cast<float2*>(po + (size_t)(row0 + 8) * DH + nt * 8 + 2 * tg) =
            make_float2(o[nt][2], o[nt][3]);
    }
    if (tg == 0) {
        float* pml = g_pml + (size_t)(bh * NSPLIT + sp) * 2 * N2;
        pml[row0]          = m0r;
        pml[row0 + 8]      = m1r;
        pml[N2 + row0]     = l0r;
        pml[N2 + row0 + 8] = l1r;
    }
}

// ---------------------------------------------------------------------------
// Merge partials -> g_attnh (half)
// ---------------------------------------------------------------------------
__global__ __launch_bounds__(256) void attn_merge()
{
    const int bh = blockIdx.x;
    const int b = bh / HEADS;
    const int h = bh - b * HEADS;
    const int tid = threadIdx.x;
    const int q  = tid >> 2;
    const int dq = tid & 3;

    float ms[NSPLIT], ls[NSPLIT];
    float M = -1e30f;
    #pragma unroll
    for (int s = 0; s < NSPLIT; s++) {
        const float* pml = g_pml + (size_t)(bh * NSPLIT + s) * 2 * N2;
        ms[s] = pml[q];
        ls[s] = pml[N2 + q];
        M = fmaxf(M, ms[s]);
    }
    float w[NSPLIT], lt = 0.f;
    #pragma unroll
    for (int s = 0; s < NSPLIT; s++) {
        w[s] = __expf(ms[s] - M);
        lt += ls[s] * w[s];
    }
    const float inv = 1.0f / lt;

    __half* dst = g_attnh + ((size_t)(b * N2 + q)) * DIM + h * DH + dq * 16;
    #pragma unroll
    for (int j = 0; j < 4; j++) {
        float4 acc = make_float4(0.f, 0.f, 0.f, 0.f);
        #pragma unroll
        for (int s = 0; s < NSPLIT; s++) {
            const float4 v = *reinterpret_cast<const float4*>(
                g_pO + ((size_t)(bh * NSPLIT + s) * N2 + q) * DH + dq * 16 + j * 4);
            acc.x += w[s] * v.x;
            acc.y += w[s] * v.y;
            acc.z += w[s] * v.z;
            acc.w += w[s] * v.w;
        }
        __half2 h0 = make_half2(__float2half_rn(acc.x * inv), __float2half_rn(acc.y * inv));
        __half2 h1 = make_half2(__float2half_rn(acc.z * inv), __float2half_rn(acc.w * inv));
        *reinterpret_cast<__half2*>(dst + j * 4)     = h0;
        *reinterpret_cast<__half2*>(dst + j * 4 + 2) = h1;
    }
}

// ---------------------------------------------------------------------------
// Launch (single stream, serial)
// ---------------------------------------------------------------------------
extern "C" void kernel_launch(void* const* d_in, const int* in_sizes, int n_in,
                              void* d_out, int out_size)
{
    const float* x       = (const float*)d_in[0];
    const float* latents = (const float*)d_in[1];
    const float* mask    = (const float*)d_in[2];
    const float* ln1g    = (const float*)d_in[3];
    const float* ln1b    = (const float*)d_in[4];
    const float* ln2g    = (const float*)d_in[5];
    const float* ln2b    = (const float*)d_in[6];
    const float* Wq      = (const float*)d_in[7];
    const float* Wkv     = (const float*)d_in[8];
    const float* Wout    = (const float*)d_in[9];
    float* out = (float*)d_out;

    __half *p_attnh, *p_wkvT, *p_wqT, *p_woT;
    cudaGetSymbolAddress((void**)&p_attnh, g_attnh);
    cudaGetSymbolAddress((void**)&p_wkvT,  g_wkvT);
    cudaGetSymbolAddress((void**)&p_wqT,   g_wqT);
    cudaGetSymbolAddress((void**)&p_woT,   g_woT);

    static bool attr_set = false;
    if (!attr_set) {
        cudaFuncSetAttribute(gemm_fused, cudaFuncAttributeMaxDynamicSharedMemorySize,
                             GEMM_SMEM_BYTES);
        cudaFuncSetAttribute(gemm_tc_s<float>, cudaFuncAttributeMaxDynamicSharedMemorySize,
                             GEMM_S_SMEM_BYTES);
        attr_set = true;
    }

    // 0) Transpose + fp16-round weights
    transpose2_kernel<<<dim3(DIM / 32, DIM / 32, 2), dim3(32, 8)>>>(Wq, Wout, p_wqT, p_woT);
    transpose_kernel<<<dim3(2 * DIM / 32, DIM / 32), dim3(32, 8)>>>(Wkv, p_wkvT, 2 * DIM);

    // 1) LayerNorms (half outputs; 4 rows per block)
    ln_kernel<<<MROWS / 4, 256>>>(x, latents, ln1g, ln1b, ln2g, ln2b);

    // 2) Fused KV + Q GEMM (KV tiles + 4 extra y-rows for Q)
    gemm_fused<<<dim3(2 * DIM / 128, KV_YTILES + BATCH * N2 / 128), 128, GEMM_SMEM_BYTES>>>();

    // 3) Attention: fp16-MMA split-K partials + merge
    attn_partial<<<dim3(HEADS, BATCH, NSPLIT), 128>>>(mask);
    attn_merge<<<BATCH * HEADS, 256>>>();

    // 4) Out GEMM (small tiles, float output) -> d_out
    gemm_tc_s<float><<<dim3(DIM / 64, BATCH * N2 / 64), 256, GEMM_S_SMEM_BYTES>>>(
        p_attnh, p_woT, out, DIM);
}

// round 17
// speedup vs baseline: 1.5928x; 1.0020x over previous
#include <cuda_runtime.h>
#include <cuda_fp16.h>
#include <cstdint>

// ---------------------------------------------------------------------------
// PerceiverAttention, sm_103 — Round 15:
//   * gemm_fused: double-buffered ldmatrix fragments — kk+1 fragment loads
//     issue BEFORE kk's MMA burst, hiding LDSM latency under tensor work
// ---------------------------------------------------------------------------

#define BATCH 8
#define N1 4096
#define N2 64
#define NKEYS 4160
#define DIM 1024
#define HEADS 16
#define DH 64
#define MROWS (BATCH * NKEYS)   // 33280
#define NSPLIT 5
#define CH_PER_SPLIT 13
#define KV_YTILES (MROWS / 128) // 260

__device__ __half g_kvin[(size_t)MROWS * DIM];
__device__ __half g_lnh [(size_t)BATCH * N2 * DIM];
__device__ __half g_qh  [(size_t)BATCH * N2 * DIM];
__device__ __half g_kvh [(size_t)MROWS * 2 * DIM];
__device__ __half g_attnh[(size_t)BATCH * N2 * DIM];
__device__ __half g_wkvT[(size_t)2 * DIM * DIM];
__device__ __half g_wqT [(size_t)DIM * DIM];
__device__ __half g_woT [(size_t)DIM * DIM];
__device__ float  g_pO  [(size_t)BATCH * HEADS * NSPLIT * N2 * DH];
__device__ float  g_pml [(size_t)BATCH * HEADS * NSPLIT * 2 * N2];

// ---------------------------------------------------------------------------
// Helpers
// ---------------------------------------------------------------------------
__device__ __forceinline__ uint32_t smem_u32(const void* p) {
    uint32_t a;
    asm("{ .reg .u64 t; cvta.to.shared.u64 t, %1; cvt.u32.u64 %0, t; }" : "=r"(a) : "l"(p));
    return a;
}
__device__ __forceinline__ void cp_async16(uint32_t dst, const void* src) {
    asm volatile("cp.async.cg.shared.global [%0], [%1], 16;" :: "r"(dst), "l"(src));
}
__device__ __forceinline__ void cp_commit() {
    asm volatile("cp.async.commit_group;" ::: "memory");
}
template <int N>
__device__ __forceinline__ void cp_wait() {
    asm volatile("cp.async.wait_group %0;" :: "n"(N) : "memory");
}
__device__ __forceinline__ void mma_f16(float* d, const uint32_t* a, const uint32_t* b) {
    asm volatile(
        "mma.sync.aligned.m16n8k16.row.col.f32.f16.f16.f32 "
        "{%0,%1,%2,%3}, {%4,%5,%6,%7}, {%8,%9}, {%0,%1,%2,%3};"
        : "+f"(d[0]), "+f"(d[1]), "+f"(d[2]), "+f"(d[3])
        : "r"(a[0]), "r"(a[1]), "r"(a[2]), "r"(a[3]), "r"(b[0]), "r"(b[1]));
}
__device__ __forceinline__ void ldm_x4(uint32_t* r, uint32_t addr) {
    asm volatile("ldmatrix.sync.aligned.m8n8.x4.shared.b16 {%0,%1,%2,%3}, [%4];"
        : "=r"(r[0]), "=r"(r[1]), "=r"(r[2]), "=r"(r[3]) : "r"(addr));
}
__device__ __forceinline__ void ldm_x4_t(uint32_t* r, uint32_t addr) {
    asm volatile("ldmatrix.sync.aligned.m8n8.x4.trans.shared.b16 {%0,%1,%2,%3}, [%4];"
        : "=r"(r[0]), "=r"(r[1]), "=r"(r[2]), "=r"(r[3]) : "r"(addr));
}
__device__ __forceinline__ uint32_t pack_h2(float a, float b) {
    __half2 h = __floats2half2_rn(a, b);
    return *reinterpret_cast<uint32_t*>(&h);
}
__device__ __forceinline__ void store_pair(float* p, float a, float b) {
    *reinterpret_cast<float2*>(p) = make_float2(a, b);
}
__device__ __forceinline__ void store_pair(__half* p, float a, float b) {
    *reinterpret_cast<__half2*>(p) = make_half2(__float2half_rn(a), __float2half_rn(b));
}

// ---------------------------------------------------------------------------
// Weight transposes
// ---------------------------------------------------------------------------
__global__ __launch_bounds__(256) void transpose_kernel(
    const float* __restrict__ in, __half* __restrict__ out, int ncols)
{
    __shared__ float t[32][33];
    const int bx = blockIdx.x * 32;
    const int by = blockIdx.y * 32;
    const int x = threadIdx.x;
    const int y = threadIdx.y;
    #pragma unroll
    for (int i = 0; i < 32; i += 8)
        t[y + i][x] = in[(size_t)(by + y + i) * ncols + bx + x];
    __syncthreads();
    #pragma unroll
    for (int i = 0; i < 32; i += 8)
        out[(size_t)(bx + y + i) * DIM + by + x] = __float2half_rn(t[x][y + i]);
}

__global__ __launch_bounds__(256) void transpose2_kernel(
    const float* __restrict__ inq, const float* __restrict__ ino,
    __half* __restrict__ outq, __half* __restrict__ outo)
{
    __shared__ float t[32][33];
    const float* in  = blockIdx.z ? ino  : inq;
    __half*      out = blockIdx.z ? outo : outq;
    const int bx = blockIdx.x * 32;
    const int by = blockIdx.y * 32;
    const int x = threadIdx.x;
    const int y = threadIdx.y;
    #pragma unroll
    for (int i = 0; i < 32; i += 8)
        t[y + i][x] = in[(size_t)(by + y + i) * DIM + bx + x];
    __syncthreads();
    #pragma unroll
    for (int i = 0; i < 32; i += 8)
        out[(size_t)(bx + y + i) * DIM + by + x] = __float2half_rn(t[x][y + i]);
}

// ---------------------------------------------------------------------------
// LayerNorm -> half outputs. 4 rows/block, 64 threads/row (MLP=4).
// ---------------------------------------------------------------------------
__global__ __launch_bounds__(256) void ln_kernel(
    const float* __restrict__ x, const float* __restrict__ lat,
    const float* __restrict__ g1, const float* __restrict__ b1,
    const float* __restrict__ g2, const float* __restrict__ b2)
{
    __shared__ float red[16];
    const int rid  = threadIdx.x >> 6;
    const int tl   = threadIdx.x & 63;
    const int wid  = threadIdx.x >> 5;
    const int lane = threadIdx.x & 31;

    const int r  = blockIdx.x * 4 + rid;
    const int bb = r / NKEYS;
    const int i  = r - bb * NKEYS;

    const float* src;
    const float* g;
    const float* be;
    __half* dst2 = nullptr;
    if (i < N1) {
        src = x + ((size_t)bb * N1 + i) * DIM;
        g = g1; be = b1;
    } else {
        const int j = i - N1;
        src = lat + ((size_t)bb * N2 + j) * DIM;
        g = g2; be = b2;
        dst2 = g_lnh + ((size_t)bb * N2 + j) * DIM;
    }
    __half* dst = g_kvin + (size_t)r * DIM;

    const float4* s4 = reinterpret_cast<const float4*>(src);
    float4 v[4];
    #pragma unroll
    for (int p = 0; p < 4; p++) v[p] = s4[tl + 64 * p];

    float s = 0.f, sq = 0.f;
    #pragma unroll
    for (int p = 0; p < 4; p++) {
        s  += v[p].x + v[p].y + v[p].z + v[p].w;
        sq += v[p].x*v[p].x + v[p].y*v[p].y + v[p].z*v[p].z + v[p].w*v[p].w;
    }
    #pragma unroll
    for (int o = 16; o > 0; o >>= 1) {
        s  += __shfl_xor_sync(0xffffffffu, s, o);
        sq += __shfl_xor_sync(0xffffffffu, sq, o);
    }
    if (lane == 0) { red[wid * 2] = s; red[wid * 2 + 1] = sq; }
    __syncthreads();
    const float S  = red[rid * 4]     + red[rid * 4 + 2];
    const float SQ = red[rid * 4 + 1] + red[rid * 4 + 3];

    const float mu   = S * (1.0f / DIM);
    const float var  = SQ * (1.0f / DIM) - mu * mu;
    const float rstd = rsqrtf(var + 1e-5f);

    const float4* g4 = reinterpret_cast<const float4*>(g);
    const float4* b4 = reinterpret_cast<const float4*>(be);
    #pragma unroll
    for (int p = 0; p < 4; p++) {
        const float4 gv = g4[tl + 64 * p];
        const float4 bv = b4[tl + 64 * p];
        uint2 u;
        __half2* hp = reinterpret_cast<__half2*>(&u);
        hp[0] = make_half2(__float2half_rn((v[p].x - mu) * rstd * gv.x + bv.x),
                           __float2half_rn((v[p].y - mu) * rstd * gv.y + bv.y));
        hp[1] = make_half2(__float2half_rn((v[p].z - mu) * rstd * gv.z + bv.z),
                           __float2half_rn((v[p].w - mu) * rstd * gv.w + bv.w));
        reinterpret_cast<uint2*>(dst)[tl + 64 * p] = u;
        if (dst2) reinterpret_cast<uint2*>(dst2)[tl + 64 * p] = u;
    }
}

// ---------------------------------------------------------------------------
// Fused KV+Q GEMM: 128x128 CTA tile, 128 threads (4 warps of 64x64),
// 3-stage cp.async, one barrier/chunk, double-buffered ldmatrix fragments.
// ---------------------------------------------------------------------------
#define PADH 72
#define TILE_H (128 * PADH)
#define NSTAGE 3
#define GEMM_SMEM_BYTES (NSTAGE * 2 * TILE_H * 2)   // 110592

__global__ __launch_bounds__(128, 2) void gemm_fused(void)
{
    extern __shared__ __half smh[];
    const uint32_t sb = smem_u32(smh);

    const int by = blockIdx.y;
    const int bx = blockIdx.x;
    const __half* A;
    const __half* Bt;
    __half* C;
    int ldc, m0;
    if (by < KV_YTILES) {
        A = g_kvin; Bt = g_wkvT; C = g_kvh; ldc = 2 * DIM; m0 = by * 128;
    } else {
        if (bx >= DIM / 128) return;
        A = g_lnh;  Bt = g_wqT;  C = g_qh;  ldc = DIM;     m0 = (by - KV_YTILES) * 128;
    }
    const int n0 = bx * 128;

    const int tid  = threadIdx.x;
    const int wid  = tid >> 5;
    const int lane = tid & 31;
    const int wm = wid & 1;
    const int wn = wid >> 1;

    const __half* ga = A  + (size_t)m0 * DIM;
    const __half* gb = Bt + (size_t)n0 * DIM;

    const int lr = tid >> 3;
    const int lc = tid & 7;

    float acc[4][8][4];
    #pragma unroll
    for (int i = 0; i < 4; i++)
        #pragma unroll
        for (int j = 0; j < 8; j++)
            #pragma unroll
            for (int q = 0; q < 4; q++) acc[i][j][q] = 0.f;

    const uint32_t a_off = (uint32_t)(wm * 64 + (lane & 15)) * PADH + (lane >> 4) * 8;
    const uint32_t b_off = (uint32_t)(wn * 64 + ((lane >> 4) << 3) + (lane & 7)) * PADH
                         + ((lane >> 3) & 1) * 8;

    auto load_tile = [&](int chunk, int stage) {
        const uint32_t abase = sb + (uint32_t)stage * 2 * TILE_H * 2;
        const uint32_t bbase = abase + TILE_H * 2;
        const int k0 = chunk * 64;
        #pragma unroll
        for (int i = 0; i < 8; i++) {
            const int r = lr + i * 16;
            cp_async16(abase + (r * PADH + lc * 8) * 2, ga + (size_t)r * DIM + k0 + lc * 8);
        }
        #pragma unroll
        for (int i = 0; i < 8; i++) {
            const int r = lr + i * 16;
            cp_async16(bbase + (r * PADH + lc * 8) * 2, gb + (size_t)r * DIM + k0 + lc * 8);
        }
        cp_commit();
    };

    // Fragment loader: kk-th 16-wide k-slice from stage base addresses
    auto ldfrag = [&](uint32_t sA, uint32_t sB, int kk,
                      uint32_t af[4][4], uint32_t bf[8][2]) {
        #pragma unroll
        for (int mt = 0; mt < 4; mt++)
            ldm_x4(af[mt], sA + (a_off + (uint32_t)(mt * 16) * PADH + kk * 16) * 2);
        #pragma unroll
        for (int p = 0; p < 4; p++) {
            uint32_t r4[4];
            ldm_x4(r4, sB + (b_off + (uint32_t)(p * 16) * PADH + kk * 16) * 2);
            bf[2 * p][0]     = r4[0];
            bf[2 * p][1]     = r4[1];
            bf[2 * p + 1][0] = r4[2];
            bf[2 * p + 1][1] = r4[3];
        }
    };

    const int NCHUNK = DIM / 64;   // 16
    load_tile(0, 0);
    load_tile(1, 1);

    uint32_t af[2][4][4], bf[2][8][2];

    for (int c = 0; c < NCHUNK; c++) {
        const int stage = c % NSTAGE;
        if (c == NCHUNK - 1) cp_wait<0>();
        else                 cp_wait<1>();
        __syncthreads();
        if (c + 2 < NCHUNK) load_tile(c + 2, (c + 2) % NSTAGE);

        const uint32_t sA = sb + (uint32_t)stage * 2 * TILE_H * 2;
        const uint32_t sB = sA + TILE_H * 2;

        ldfrag(sA, sB, 0, af[0], bf[0]);
        #pragma unroll
        for (int kk = 0; kk < 4; kk++) {
            const int cur = kk & 1;
            if (kk < 3) ldfrag(sA, sB, kk + 1, af[cur ^ 1], bf[cur ^ 1]);
            #pragma unroll
            for (int mt = 0; mt < 4; mt++)
                #pragma unroll
                for (int nt = 0; nt < 8; nt++)
                    mma_f16(acc[mt][nt], af[cur][mt], bf[cur][nt]);
        }
    }

    #pragma unroll
    for (int mt = 0; mt < 4; mt++) {
        const int row = m0 + wm * 64 + mt * 16 + (lane >> 2);
        #pragma unroll
        for (int nt = 0; nt < 8; nt++) {
            const int col = n0 + wn * 64 + nt * 8 + (lane & 3) * 2;
            store_pair(C + (size_t)row * ldc + col, acc[mt][nt][0], acc[mt][nt][1]);
            store_pair(C + (size_t)(row + 8) * ldc + col, acc[mt][nt][2], acc[mt][nt][3]);
        }
    }
}

// ---------------------------------------------------------------------------
// Small-tile fp16 GEMM (64x64 CTA tile) — Out GEMM
// ---------------------------------------------------------------------------
#define TILE_HS (64 * PADH)
#define GEMM_S_SMEM_BYTES (NSTAGE * 2 * TILE_HS * 2)   // 55296

template <typename OutT>
__global__ __launch_bounds__(256, 2) void gemm_tc_s(
    const __half* __restrict__ A, const __half* __restrict__ Bt,
    OutT* __restrict__ C, int ldc)
{
    extern __shared__ __half smh[];
    const uint32_t sb = smem_u32(smh);

    const int tid  = threadIdx.x;
    const int wid  = tid >> 5;
    const int lane = tid & 31;
    const int wm = wid & 3;
    const int wn = wid >> 2;
    const int m0 = blockIdx.y * 64;
    const int n0 = blockIdx.x * 64;

    const __half* ga = A  + (size_t)m0 * DIM;
    const __half* gb = Bt + (size_t)n0 * DIM;

    const int lr = tid >> 3;
    const int lc = tid & 7;

    float acc[4][4];
    #pragma unroll
    for (int j = 0; j < 4; j++)
        #pragma unroll
        for (int q = 0; q < 4; q++) acc[j][q] = 0.f;

    const uint32_t a_off = (uint32_t)(wm * 16 + (lane & 15)) * PADH + (lane >> 4) * 8;
    const uint32_t b_off = (uint32_t)(wn * 32 + ((lane >> 4) << 3) + (lane & 7)) * PADH
                         + ((lane >> 3) & 1) * 8;

    auto load_tile = [&](int chunk, int stage) {
        const uint32_t abase = sb + (uint32_t)stage * 2 * TILE_HS * 2;
        const uint32_t bbase = abase + TILE_HS * 2;
        const int k0 = chunk * 64;
        #pragma unroll
        for (int i = 0; i < 2; i++) {
            const int r = lr + i * 32;
            cp_async16(abase + (r * PADH + lc * 8) * 2, ga + (size_t)r * DIM + k0 + lc * 8);
        }
        #pragma unroll
        for (int i = 0; i < 2; i++) {
            const int r = lr + i * 32;
            cp_async16(bbase + (r * PADH + lc * 8) * 2, gb + (size_t)r * DIM + k0 + lc * 8);
        }
        cp_commit();
    };

    const int NCHUNK = DIM / 64;
    load_tile(0, 0);
    load_tile(1, 1);

    for (int c = 0; c < NCHUNK; c++) {
        const int stage = c % NSTAGE;
        if (c == NCHUNK - 1) cp_wait<0>();
        else                 cp_wait<1>();
        __syncthreads();
        if (c + 2 < NCHUNK) load_tile(c + 2, (c + 2) % NSTAGE);

        const uint32_t sA = sb + (uint32_t)stage * 2 * TILE_HS * 2;
        const uint32_t sB = sA + TILE_HS * 2;

        #pragma unroll
        for (int kk = 0; kk < 4; kk++) {
            uint32_t af[4], bf[4][2];
            ldm_x4(af, sA + (a_off + kk * 16) * 2);
            #pragma unroll
            for (int p = 0; p < 2; p++) {
                uint32_t r4[4];
                ldm_x4(r4, sB + (b_off + (uint32_t)(p * 16) * PADH + kk * 16) * 2);
                bf[2 * p][0]     = r4[0];
                bf[2 * p][1]     = r4[1];
                bf[2 * p + 1][0] = r4[2];
                bf[2 * p + 1][1] = r4[3];
            }
            #pragma unroll
            for (int nt = 0; nt < 4; nt++)
                mma_f16(acc[nt], af, bf[nt]);
        }
    }

    const int row = m0 + wm * 16 + (lane >> 2);
    #pragma unroll
    for (int nt = 0; nt < 4; nt++) {
        const int col = n0 + wn * 32 + nt * 8 + (lane & 3) * 2;
        store_pair(C + (size_t)row * ldc + col, acc[nt][0], acc[nt][1]);
        store_pair(C + (size_t)(row + 8) * ldc + col, acc[nt][2], acc[nt][3]);
    }
}

// ---------------------------------------------------------------------------
// Split-K flash attention on fp16 mma.sync (unchanged)
// ---------------------------------------------------------------------------
#define APAD 72

__global__ __launch_bounds__(128) void attn_partial(const float* __restrict__ mask)
{
    __shared__ __half qs [64 * APAD];
    __shared__ __half ks [64 * APAD];
    __shared__ __half vsk[64 * APAD];
    __shared__ float bias[64];

    const int h = blockIdx.x;
    const int b = blockIdx.y;
    const int sp = blockIdx.z;
    const int bh = b * HEADS + h;
    const int tid = threadIdx.x;
    const int wid = tid >> 5;
    const int lane = tid & 31;
    const uint32_t sq = smem_u32(qs);
    const uint32_t sk = smem_u32(ks);
    const uint32_t sv = smem_u32(vsk);

    {
        const int q = tid >> 1;
        const int d0 = (tid & 1) * 32;
        const uint4* src = reinterpret_cast<const uint4*>(
            g_qh + (size_t)(b * N2 + q) * DIM + h * DH + d0);
        const __half2 s2 = __half2half2(__float2half(0.125f));
        #pragma unroll
        for (int i = 0; i < 4; i++) {
            uint4 u = src[i];
            __half2* hp = reinterpret_cast<__half2*>(&u);
            #pragma unroll
            for (int j = 0; j < 4; j++) hp[j] = __hmul2(hp[j], s2);
            *reinterpret_cast<uint4*>(qs + q * APAD + d0 + i * 8) = u;
        }
    }

    float o[8][4];
    #pragma unroll
    for (int j = 0; j < 8; j++)
        #pragma unroll
        for (int q = 0; q < 4; q++) o[j][q] = 0.f;
    float m0r = -1e30f, m1r = -1e30f, l0r = 0.f, l1r = 0.f;

    const uint32_t a_off = (uint32_t)(wid * 16 + (lane & 15)) * APAD + (lane >> 4) * 8;
    const uint32_t b_off = (uint32_t)(((lane >> 4) << 3) + (lane & 7)) * APAD
                         + ((lane >> 3) & 1) * 8;
    const uint32_t t_off = (uint32_t)(((lane >> 3) & 1) * 8 + (lane & 7)) * APAD
                         + (lane >> 4) * 8;
    const int tg = lane & 3;

    for (int cc = 0; cc < CH_PER_SPLIT; cc++) {
        const int key0 = (sp * CH_PER_SPLIT + cc) * 64;
        __syncthreads();

        {
            const int row = tid >> 1;
            const int cb = (tid & 1) * 4;
            const __half* ksrc = g_kvh + ((size_t)(b * NKEYS) + key0 + row) * (2 * DIM) + h * DH;
            const __half* vsrc = ksrc + DIM;
            #pragma unroll
            for (int i = 0; i < 4; i++)
                cp_async16(sk + (row * APAD + (cb + i) * 8) * 2, ksrc + (cb + i) * 8);
            #pragma unroll
            for (int i = 0; i < 4; i++)
                cp_async16(sv + (row * APAD + (cb + i) * 8) * 2, vsrc + (cb + i) * 8);
            cp_commit();
        }
        if (tid < 64) {
            const int kg = key0 + tid;
            bias[tid] = (kg < N1) ? (mask[(size_t)b * N1 + kg] - 1.0f) * 100.0f : 0.f;
        }
        cp_wait<0>();
        __syncthreads();

        float s[8][4];
        #pragma unroll
        for (int j = 0; j < 8; j++)
            #pragma unroll
            for (int q = 0; q < 4; q++) s[j][q] = 0.f;
        #pragma unroll
        for (int kk = 0; kk < 4; kk++) {
            uint32_t af[4], bf[8][2];
            ldm_x4(af, sq + (a_off + kk * 16) * 2);
            #pragma unroll
            for (int p = 0; p < 4; p++) {
                uint32_t r4[4];
                ldm_x4(r4, sk + (b_off + (uint32_t)(p * 16) * APAD + kk * 16) * 2);
                bf[2 * p][0]     = r4[0];
                bf[2 * p][1]     = r4[1];
                bf[2 * p + 1][0] = r4[2];
                bf[2 * p + 1][1] = r4[3];
            }
            #pragma unroll
            for (int nt = 0; nt < 8; nt++)
                mma_f16(s[nt], af, bf[nt]);
        }

        float c0 = -1e30f, c1 = -1e30f;
        #pragma unroll
        for (int nt = 0; nt < 8; nt++) {
            const float b0 = bias[nt * 8 + 2 * tg];
            const float b1 = bias[nt * 8 + 2 * tg + 1];
            s[nt][0] += b0; s[nt][1] += b1; s[nt][2] += b0; s[nt][3] += b1;
            c0 = fmaxf(c0, fmaxf(s[nt][0], s[nt][1]));
            c1 = fmaxf(c1, fmaxf(s[nt][2], s[nt][3]));
        }
        c0 = fmaxf(c0, __shfl_xor_sync(0xffffffffu, c0, 1));
        c0 = fmaxf(c0, __shfl_xor_sync(0xffffffffu, c0, 2));
        c1 = fmaxf(c1, __shfl_xor_sync(0xffffffffu, c1, 1));
        c1 = fmaxf(c1, __shfl_xor_sync(0xffffffffu, c1, 2));

        const float mn0 = fmaxf(m0r, c0);
        const float mn1 = fmaxf(m1r, c1);
        const float al0 = __expf(m0r - mn0);
        const float al1 = __expf(m1r - mn1);
        float cs0 = 0.f, cs1 = 0.f;
        #pragma unroll
        for (int nt = 0; nt < 8; nt++) {
            s[nt][0] = __expf(s[nt][0] - mn0); cs0 += s[nt][0];
            s[nt][1] = __expf(s[nt][1] - mn0); cs0 += s[nt][1];
            s[nt][2] = __expf(s[nt][2] - mn1); cs1 += s[nt][2];
            s[nt][3] = __expf(s[nt][3] - mn1); cs1 += s[nt][3];
        }
        cs0 += __shfl_xor_sync(0xffffffffu, cs0, 1);
        cs0 += __shfl_xor_sync(0xffffffffu, cs0, 2);
        cs1 += __shfl_xor_sync(0xffffffffu, cs1, 1);
        cs1 += __shfl_xor_sync(0xffffffffu, cs1, 2);
        l0r = l0r * al0 + cs0; m0r = mn0;
        l1r = l1r * al1 + cs1; m1r = mn1;
        #pragma unroll
        for (int nt = 0; nt < 8; nt++) {
            o[nt][0] *= al0; o[nt][1] *= al0;
            o[nt][2] *= al1; o[nt][3] *= al1;
        }

        #pragma unroll
        for (int kv = 0; kv < 4; kv++) {
            uint32_t pa[4];
            pa[0] = pack_h2(s[2 * kv][0],     s[2 * kv][1]);
            pa[1] = pack_h2(s[2 * kv][2],     s[2 * kv][3]);
            pa[2] = pack_h2(s[2 * kv + 1][0], s[2 * kv + 1][1]);
            pa[3] = pack_h2(s[2 * kv + 1][2], s[2 * kv + 1][3]);
            uint32_t bf[8][2];
            #pragma unroll
            for (int p = 0; p < 4; p++) {
                uint32_t r4[4];
                ldm_x4_t(r4, sv + (t_off + (uint32_t)(kv * 16) * APAD + p * 16) * 2);
                bf[2 * p][0]     = r4[0];
                bf[2 * p][1]     = r4[1];
                bf[2 * p + 1][0] = r4[2];
                bf[2 * p + 1][1] = r4[3];
            }
            #pragma unroll
            for (int nt = 0; nt < 8; nt++)
                mma_f16(o[nt], pa, bf[nt]);
        }
    }

    const int g = lane >> 2;
    const int row0 = wid * 16 + g;
    float* po = g_pO + ((size_t)(bh * NSPLIT + sp) * N2) * DH;
    #pragma unroll
    for (int nt = 0; nt < 8; nt++) {
        *reinterpret_cast<float2*>(po + (size_t)row0 * DH + nt * 8 + 2 * tg) =
            make_float2(o[nt][0], o[nt][1]);
        *reinterpret_cast<float2*>(po + (size_t)(row0 + 8) * DH + nt * 8 + 2 * tg) =
            make_float2(o[nt][2], o[nt][3]);
    }
    if (tg == 0) {
        float* pml = g_pml + (size_t)(bh * NSPLIT + sp) * 2 * N2;
        pml[row0]          = m0r;
        pml[row0 + 8]      = m1r;
        pml[N2 + row0]     = l0r;
        pml[N2 + row0 + 8] = l1r;
    }
}

// ---------------------------------------------------------------------------
// Merge partials -> g_attnh (half)
// ---------------------------------------------------------------------------
__global__ __launch_bounds__(256) void attn_merge()
{
    const int bh = blockIdx.x;
    const int b = bh / HEADS;
    const int h = bh - b * HEADS;
    const int tid = threadIdx.x;
    const int q  = tid >> 2;
    const int dq = tid & 3;

    float ms[NSPLIT], ls[NSPLIT];
    float M = -1e30f;
    #pragma unroll
    for (int s = 0; s < NSPLIT; s++) {
        const float* pml = g_pml + (size_t)(bh * NSPLIT + s) * 2 * N2;
        ms[s] = pml[q];
        ls[s] = pml[N2 + q];
        M = fmaxf(M, ms[s]);
    }
    float w[NSPLIT], lt = 0.f;
    #pragma unroll
    for (int s = 0; s < NSPLIT; s++) {
        w[s] = __expf(ms[s] - M);
        lt += ls[s] * w[s];
    }
    const float inv = 1.0f / lt;

    __half* dst = g_attnh + ((size_t)(b * N2 + q)) * DIM + h * DH + dq * 16;
    #pragma unroll
    for (int j = 0; j < 4; j++) {
        float4 acc = make_float4(0.f, 0.f, 0.f, 0.f);
        #pragma unroll
        for (int s = 0; s < NSPLIT; s++) {
            const float4 v = *reinterpret_cast<const float4*>(
                g_pO + ((size_t)(bh * NSPLIT + s) * N2 + q) * DH + dq * 16 + j * 4);
            acc.x += w[s] * v.x;
            acc.y += w[s] * v.y;
            acc.z += w[s] * v.z;
            acc.w += w[s] * v.w;
        }
        __half2 h0 = make_half2(__float2half_rn(acc.x * inv), __float2half_rn(acc.y * inv));
        __half2 h1 = make_half2(__float2half_rn(acc.z * inv), __float2half_rn(acc.w * inv));
        *reinterpret_cast<__half2*>(dst + j * 4)     = h0;
        *reinterpret_cast<__half2*>(dst + j * 4 + 2) = h1;
    }
}

// ---------------------------------------------------------------------------
// Launch (single stream, serial)
// ---------------------------------------------------------------------------
extern "C" void kernel_launch(void* const* d_in, const int* in_sizes, int n_in,
                              void* d_out, int out_size)
{
    const float* x       = (const float*)d_in[0];
    const float* latents = (const float*)d_in[1];
    const float* mask    = (const float*)d_in[2];
    const float* ln1g    = (const float*)d_in[3];
    const float* ln1b    = (const float*)d_in[4];
    const float* ln2g    = (const float*)d_in[5];
    const float* ln2b    = (const float*)d_in[6];
    const float* Wq      = (const float*)d_in[7];
    const float* Wkv     = (const float*)d_in[8];
    const float* Wout    = (const float*)d_in[9];
    float* out = (float*)d_out;

    __half *p_attnh, *p_wkvT, *p_wqT, *p_woT;
    cudaGetSymbolAddress((void**)&p_attnh, g_attnh);
    cudaGetSymbolAddress((void**)&p_wkvT,  g_wkvT);
    cudaGetSymbolAddress((void**)&p_wqT,   g_wqT);
    cudaGetSymbolAddress((void**)&p_woT,   g_woT);

    static bool attr_set = false;
    if (!attr_set) {
        cudaFuncSetAttribute(gemm_fused, cudaFuncAttributeMaxDynamicSharedMemorySize,
                             GEMM_SMEM_BYTES);
        cudaFuncSetAttribute(gemm_tc_s<float>, cudaFuncAttributeMaxDynamicSharedMemorySize,
                             GEMM_S_SMEM_BYTES);
        attr_set = true;
    }

    // 0) Transpose + fp16-round weights
    transpose2_kernel<<<dim3(DIM / 32, DIM / 32, 2), dim3(32, 8)>>>(Wq, Wout, p_wqT, p_woT);
    transpose_kernel<<<dim3(2 * DIM / 32, DIM / 32), dim3(32, 8)>>>(Wkv, p_wkvT, 2 * DIM);

    // 1) LayerNorms (half outputs; 4 rows per block)
    ln_kernel<<<MROWS / 4, 256>>>(x, latents, ln1g, ln1b, ln2g, ln2b);

    // 2) Fused KV + Q GEMM
    gemm_fused<<<dim3(2 * DIM / 128, KV_YTILES + BATCH * N2 / 128), 128, GEMM_SMEM_BYTES>>>();

    // 3) Attention: fp16-MMA split-K partials + merge
    attn_partial<<<dim3(HEADS, BATCH, NSPLIT), 128>>>(mask);
    attn_merge<<<BATCH * HEADS, 256>>>();

    // 4) Out GEMM (small tiles, float output) -> d_out
    gemm_tc_s<float><<<dim3(DIM / 64, BATCH * N2 / 64), 256, GEMM_S_SMEM_BYTES>>>(
        p_attnh, p_woT, out, DIM);
}